// round 2
// baseline (speedup 1.0000x reference)
#include <cuda_runtime.h>
#include <cstdint>

#define B_ 2048
#define T_ 18
#define C_ 128
#define D_ 4096
#define P_ 32

// ---------------- scratch (device globals; no allocation allowed) ----------
__device__ float g_pred[T_ * B_ * C_];   // [t][b][c]  18.9 MB
__device__ float g_enc [T_ * B_ * C_];   // [t][b][c]  18.9 MB
__device__ float g_h   [B_ * C_];        // [b][c]
__device__ float g_mean[C_];
__device__ float g_rstd[C_];
__device__ float g_nce;

// ---------------- init: transpose z_aug2 [B,C,T] -> enc [T,B,C]; zero nce --
__global__ void init_kernel(const float* __restrict__ z)
{
    int bc = blockIdx.x * blockDim.x + threadIdx.x;   // 0 .. B*C-1
    if (bc == 0) g_nce = 0.0f;
    if (bc < B_ * C_) {
        const float* src = z + (size_t)bc * T_;
#pragma unroll
        for (int t = 0; t < T_; t++)
            g_enc[(size_t)t * B_ * C_ + bc] = src[t];
    }
}

// ---------------- GEMM: [2048 x 4096] @ [2432 x 4096]^T + bias ------------
// blockIdx.x = 0..17 -> Wk_w timestep t (out -> g_pred[t]); 18 -> pw1 (out -> g_h)
// blockIdx.y = row tile (128 rows)
__global__ __launch_bounds__(256, 2) void gemm_kernel(
    const float* __restrict__ A,      // c_t [B, D]
    const float* __restrict__ Wk_w,   // [T, C, D]
    const float* __restrict__ Wk_b,   // [T, C]
    const float* __restrict__ pw1,    // [C, D]
    const float* __restrict__ pb1)    // [C]
{
    const int tb = blockIdx.x;
    const int rowBase = blockIdx.y * 128;

    const float* W;
    const float* bias;
    float* out;
    if (tb < T_) {
        W    = Wk_w + (size_t)tb * C_ * D_;
        bias = Wk_b + tb * C_;
        out  = g_pred + (size_t)tb * B_ * C_;
    } else {
        W    = pw1;
        bias = pb1;
        out  = g_h;
    }

    __shared__ float As[16][132];   // [k][m]
    __shared__ float Ws[16][132];   // [k][n]

    const int tid = threadIdx.x;
    const int ty  = tid >> 4;       // 0..15  -> rows ty*8..+7
    const int tx  = tid & 15;       // 0..15  -> cols tx*8..+7

    float acc[8][8];
#pragma unroll
    for (int i = 0; i < 8; i++)
#pragma unroll
        for (int j = 0; j < 8; j++) acc[i][j] = 0.0f;

    for (int k0 = 0; k0 < D_; k0 += 16) {
#pragma unroll
        for (int i = 0; i < 2; i++) {
            int f  = tid + i * 256;       // 0..511
            int r  = f >> 2;              // 0..127
            int kq = (f & 3) << 2;        // 0,4,8,12
            float4 va = *(const float4*)(A + (size_t)(rowBase + r) * D_ + k0 + kq);
            As[kq + 0][r] = va.x; As[kq + 1][r] = va.y;
            As[kq + 2][r] = va.z; As[kq + 3][r] = va.w;
            float4 vw = *(const float4*)(W + (size_t)r * D_ + k0 + kq);
            Ws[kq + 0][r] = vw.x; Ws[kq + 1][r] = vw.y;
            Ws[kq + 2][r] = vw.z; Ws[kq + 3][r] = vw.w;
        }
        __syncthreads();
#pragma unroll
        for (int kk = 0; kk < 16; kk++) {
            float a[8], b[8];
            *(float4*)(a)     = *(const float4*)&As[kk][ty * 8];
            *(float4*)(a + 4) = *(const float4*)&As[kk][ty * 8 + 4];
            *(float4*)(b)     = *(const float4*)&Ws[kk][tx * 8];
            *(float4*)(b + 4) = *(const float4*)&Ws[kk][tx * 8 + 4];
#pragma unroll
            for (int i = 0; i < 8; i++)
#pragma unroll
                for (int j = 0; j < 8; j++)
                    acc[i][j] = fmaf(a[i], b[j], acc[i][j]);
        }
        __syncthreads();
    }

    float bj[8];
    *(float4*)(bj)     = *(const float4*)(bias + tx * 8);
    *(float4*)(bj + 4) = *(const float4*)(bias + tx * 8 + 4);
#pragma unroll
    for (int i = 0; i < 8; i++) {
        float* orow = out + (size_t)(rowBase + ty * 8 + i) * C_ + tx * 8;
        float4 v0 = make_float4(acc[i][0] + bj[0], acc[i][1] + bj[1],
                                acc[i][2] + bj[2], acc[i][3] + bj[3]);
        float4 v1 = make_float4(acc[i][4] + bj[4], acc[i][5] + bj[5],
                                acc[i][6] + bj[6], acc[i][7] + bj[7]);
        *(float4*)(orow)     = v0;
        *(float4*)(orow + 4) = v1;
    }
}

// ---------------- flash-style NCE: streaming logsumexp + diagonal ---------
// block (rb, t): rows rb*128..+127 of total[t] = enc[t] @ pred[t]^T
// smem carve (floats): Qs[128][132] | Ks[16][132] | red[128][17] | m,l,d [128]
#define FL_SMEM_FLOATS (128 * 132 + 16 * 132 + 128 * 17 + 3 * 128)

__global__ __launch_bounds__(256, 2) void flash_kernel()
{
    extern __shared__ float fsm[];
    float* Qs  = fsm;                  // [c][r]  c=0..127, stride 132
    float* Ks  = Qs + 128 * 132;       // [kk][n] kk=0..15, stride 132
    float* red = Ks + 16 * 132;        // [row][tx], stride 17
    float* m_s = red + 128 * 17;
    float* l_s = m_s + 128;
    float* d_s = l_s + 128;

    const int rb  = blockIdx.x;        // row tile 0..15
    const int t   = blockIdx.y;        // timestep 0..17
    const int tid = threadIdx.x;
    const int ty  = tid >> 4, tx = tid & 15;

    const float* enc_t  = g_enc  + ((size_t)t * B_ + rb * 128) * C_;
    const float* pred_t = g_pred + (size_t)t * B_ * C_;

    if (tid < 128) {
        m_s[tid] = -__int_as_float(0x7f800000);  // -inf
        l_s[tid] = 0.0f;
        d_s[tid] = 0.0f;
    }

    // load Q tile transposed: Qs[c][r]
    for (int f = tid; f < 128 * 32; f += 256) {
        int r = f >> 5;
        int c = (f & 31) << 2;
        float4 v = *(const float4*)(enc_t + (size_t)r * C_ + c);
        Qs[(c + 0) * 132 + r] = v.x;
        Qs[(c + 1) * 132 + r] = v.y;
        Qs[(c + 2) * 132 + r] = v.z;
        Qs[(c + 3) * 132 + r] = v.w;
    }
    __syncthreads();

    for (int kt = 0; kt < 16; kt++) {
        float acc[8][8];
#pragma unroll
        for (int i = 0; i < 8; i++)
#pragma unroll
            for (int j = 0; j < 8; j++) acc[i][j] = 0.0f;

        const float* Kbase = pred_t + (size_t)kt * 128 * C_;
        for (int c0 = 0; c0 < 128; c0 += 16) {
#pragma unroll
            for (int i = 0; i < 2; i++) {
                int f  = tid + i * 256;
                int n  = f >> 2;
                int q4 = (f & 3) << 2;
                float4 v = *(const float4*)(Kbase + (size_t)n * C_ + c0 + q4);
                Ks[(q4 + 0) * 132 + n] = v.x;
                Ks[(q4 + 1) * 132 + n] = v.y;
                Ks[(q4 + 2) * 132 + n] = v.z;
                Ks[(q4 + 3) * 132 + n] = v.w;
            }
            __syncthreads();
#pragma unroll
            for (int kk = 0; kk < 16; kk++) {
                float a[8], b[8];
                *(float4*)(a)     = *(const float4*)&Qs[(c0 + kk) * 132 + ty * 8];
                *(float4*)(a + 4) = *(const float4*)&Qs[(c0 + kk) * 132 + ty * 8 + 4];
                *(float4*)(b)     = *(const float4*)&Ks[kk * 132 + tx * 8];
                *(float4*)(b + 4) = *(const float4*)&Ks[kk * 132 + tx * 8 + 4];
#pragma unroll
                for (int i = 0; i < 8; i++)
#pragma unroll
                    for (int j = 0; j < 8; j++)
                        acc[i][j] = fmaf(a[i], b[j], acc[i][j]);
            }
            __syncthreads();
        }

        // ---- online softmax update ----
#pragma unroll
        for (int i = 0; i < 8; i++) {
            float m = acc[i][0];
#pragma unroll
            for (int j = 1; j < 8; j++) m = fmaxf(m, acc[i][j]);
            red[(ty * 8 + i) * 17 + tx] = m;
        }
        __syncthreads();
        if (tid < 128) {
            float tm = red[tid * 17];
#pragma unroll
            for (int x = 1; x < 16; x++) tm = fmaxf(tm, red[tid * 17 + x]);
            float mo = m_s[tid];
            float mn = fmaxf(mo, tm);
            l_s[tid] *= __expf(mo - mn);   // mo=-inf -> factor 0, l was 0 anyway
            m_s[tid] = mn;
        }
        __syncthreads();
#pragma unroll
        for (int i = 0; i < 8; i++) {
            float mrow = m_s[ty * 8 + i];
            float s = 0.0f;
#pragma unroll
            for (int j = 0; j < 8; j++) s += __expf(acc[i][j] - mrow);
            red[(ty * 8 + i) * 17 + tx] = s;
        }
        if (kt == rb) {   // diagonal lives in this k tile (tiles aligned)
#pragma unroll
            for (int i = 0; i < 8; i++) {
                int j = ty * 8 + i - tx * 8;
                if (j >= 0 && j < 8) d_s[ty * 8 + i] = acc[i][j];
            }
        }
        __syncthreads();
        if (tid < 128) {
            float s = 0.0f;
#pragma unroll
            for (int x = 0; x < 16; x++) s += red[tid * 17 + x];
            l_s[tid] += s;
        }
        __syncthreads();
    }

    // diag log-softmax value per row; block reduce; atomic accumulate
    float v = 0.0f;
    if (tid < 128) v = d_s[tid] - (m_s[tid] + logf(l_s[tid]));
#pragma unroll
    for (int o = 16; o > 0; o >>= 1) v += __shfl_down_sync(0xffffffffu, v, o);
    if ((tid & 31) == 0 && tid < 128) atomicAdd(&g_nce, v);
}

// ---------------- BatchNorm statistics (per channel over batch) -----------
__global__ void bnstat_kernel()
{
    const int c   = blockIdx.x;
    const int tid = threadIdx.x;
    float s = 0.0f, sq = 0.0f;
    for (int b = tid; b < B_; b += 256) {
        float v = g_h[(size_t)b * C_ + c];
        s += v;
        sq = fmaf(v, v, sq);
    }
    __shared__ float ss[256], sqq[256];
    ss[tid] = s; sqq[tid] = sq;
    __syncthreads();
    for (int st = 128; st > 0; st >>= 1) {
        if (tid < st) { ss[tid] += ss[tid + st]; sqq[tid] += sqq[tid + st]; }
        __syncthreads();
    }
    if (tid == 0) {
        float mean = ss[0] * (1.0f / B_);
        float var  = sqq[0] * (1.0f / B_) - mean * mean;
        g_mean[c] = mean;
        g_rstd[c] = rsqrtf(var + 1e-5f);
    }
}

// ---------------- projection: BN-apply + LeakyReLU + [.,128]@[128,32]^T ---
// 32 rows per block -> static smem ~34 KB (under 48 KB static limit)
__global__ void proj_kernel(const float* __restrict__ gamma,
                            const float* __restrict__ beta,
                            const float* __restrict__ pw2,   // [P, C]
                            const float* __restrict__ pb2,   // [P]
                            float* __restrict__ out)
{
    __shared__ float w2s[P_][132];    // 16.5 KB
    __shared__ float hn[32][129];     // 16.1 KB
    __shared__ float mg[C_], bg[C_];  // 1 KB

    const int tid  = threadIdx.x;
    const int base = blockIdx.x * 32;

    for (int f = tid; f < P_ * C_; f += 256) {
        int p = f >> 7, c = f & 127;
        w2s[p][c] = pw2[f];
    }
    if (tid < C_) {
        float sc = g_rstd[tid] * gamma[tid];
        mg[tid] = sc;
        bg[tid] = beta[tid] - g_mean[tid] * sc;
    }
    __syncthreads();

    for (int f = tid; f < 32 * C_; f += 256) {
        int r = f >> 7, c = f & 127;
        float v = g_h[(size_t)(base + r) * C_ + c];
        v = v * mg[c] + bg[c];
        v = (v >= 0.0f) ? v : 0.01f * v;
        hn[r][c] = v;
    }
    __syncthreads();

    const int r  = tid >> 3;          // 0..31
    const int pg = (tid & 7) * 4;     // 0,4,...,28
    float accp[4];
#pragma unroll
    for (int p = 0; p < 4; p++) accp[p] = 0.0f;
    for (int c = 0; c < C_; c++) {
        float hv = hn[r][c];
#pragma unroll
        for (int p = 0; p < 4; p++)
            accp[p] = fmaf(hv, w2s[pg + p][c], accp[p]);
    }
#pragma unroll
    for (int p = 0; p < 4; p++)
        out[1 + (size_t)(base + r) * P_ + pg + p] = accp[p] + pb2[pg + p];

    if (blockIdx.x == 0 && tid == 0)
        out[0] = g_nce * (-1.0f / (float)(B_ * T_));
}

// ---------------- launch ---------------------------------------------------
extern "C" void kernel_launch(void* const* d_in, const int* in_sizes, int n_in,
                              void* d_out, int out_size)
{
    const float* z     = (const float*)d_in[0];  // z_aug2 [B,C,T]
    const float* c_t   = (const float*)d_in[1];  // [B,D]
    const float* Wk_w  = (const float*)d_in[2];  // [T,C,D]
    const float* Wk_b  = (const float*)d_in[3];  // [T,C]
    const float* pw1   = (const float*)d_in[4];  // [C,D]
    const float* pb1   = (const float*)d_in[5];  // [C]
    const float* gamma = (const float*)d_in[6];  // [C]
    const float* beta  = (const float*)d_in[7];  // [C]
    const float* pw2   = (const float*)d_in[8];  // [P,C]
    const float* pb2   = (const float*)d_in[9];  // [P]
    float* out = (float*)d_out;

    init_kernel<<<(B_ * C_ + 255) / 256, 256>>>(z);
    gemm_kernel<<<dim3(T_ + 1, B_ / 128), 256>>>(c_t, Wk_w, Wk_b, pw1, pb1);

    size_t fl_smem = (size_t)FL_SMEM_FLOATS * sizeof(float);  // ~86 KB
    cudaFuncSetAttribute(flash_kernel,
                         cudaFuncAttributeMaxDynamicSharedMemorySize,
                         (int)fl_smem);
    flash_kernel<<<dim3(B_ / 128, T_), 256, fl_smem>>>();

    bnstat_kernel<<<C_, 256>>>();
    proj_kernel<<<B_ / 32, 256>>>(gamma, beta, pw2, pb2, out);
}

// round 4
// speedup vs baseline: 1.7065x; 1.7065x over previous
#include <cuda_runtime.h>
#include <cuda_bf16.h>
#include <cstdint>

#define B_ 2048
#define T_ 18
#define C_ 128
#define D_ 4096
#define P_ 32
#define NT 19               // 18 timesteps + pw1 block
#define NC_ (D_ / 32)       // 128 K-chunks of 32 bf16
#define AST_B 80            // smem row stride in bytes (32 bf16 + 16B pad)
#define TILE_SM (128 * AST_B)        // 10240 B per 128x32 tile
#define STAGE_SM (4 * TILE_SM)       // Ahi, Alo, Whi, Wlo
#define GEMM_SMEM (2 * STAGE_SM)     // 81920 B

// ---------------- scratch (device globals; no allocation allowed) ----------
__device__ float g_pred[T_ * B_ * C_];   // [t][b][c]
__device__ float g_enc [T_ * B_ * C_];   // [t][b][c]
__device__ float g_h   [B_ * C_];
__device__ float g_mean[C_];
__device__ float g_rstd[C_];
__device__ float g_nce;

// bf16 hi/lo tiles: [rowtile/t][kchunk][128 rows][32 cols] (row-major, 64B rows)
__device__ __align__(16) __nv_bfloat16 g_Ahi[16 * NC_ * 4096];
__device__ __align__(16) __nv_bfloat16 g_Alo[16 * NC_ * 4096];
__device__ __align__(16) __nv_bfloat16 g_Whi[NT * NC_ * 4096];
__device__ __align__(16) __nv_bfloat16 g_Wlo[NT * NC_ * 4096];

// ---------------- helpers ---------------------------------------------------
__device__ __forceinline__ uint32_t smem_u32(const void* p) {
    uint32_t a;
    asm("{ .reg .u64 t; cvta.to.shared.u64 t, %1; cvt.u32.u64 %0, t; }"
        : "=r"(a) : "l"(p));
    return a;
}

__device__ __forceinline__ void cp16(uint32_t dst, const void* src) {
    asm volatile("cp.async.cg.shared.global [%0], [%1], 16;"
                 :: "r"(dst), "l"(src) : "memory");
}
#define CP_COMMIT() asm volatile("cp.async.commit_group;" ::: "memory")
#define CP_WAIT(N)  asm volatile("cp.async.wait_group %0;" :: "n"(N) : "memory")

__device__ __forceinline__ void ldmx4(uint32_t* r, uint32_t addr) {
    asm volatile("ldmatrix.sync.aligned.m8n8.x4.shared.b16 {%0,%1,%2,%3}, [%4];"
                 : "=r"(r[0]), "=r"(r[1]), "=r"(r[2]), "=r"(r[3]) : "r"(addr));
}

__device__ __forceinline__ void mma_bf16(float* c, const uint32_t* a,
                                         const uint32_t* b) {
    asm volatile(
        "mma.sync.aligned.m16n8k16.row.col.f32.bf16.bf16.f32 "
        "{%0,%1,%2,%3}, {%4,%5,%6,%7}, {%8,%9}, {%0,%1,%2,%3};"
        : "+f"(c[0]), "+f"(c[1]), "+f"(c[2]), "+f"(c[3])
        : "r"(a[0]), "r"(a[1]), "r"(a[2]), "r"(a[3]), "r"(b[0]), "r"(b[1]));
}

// ---------------- init: transpose z_aug2 [B,C,T] -> enc [T,B,C]; zero nce --
__global__ void init_kernel(const float* __restrict__ z)
{
    int bc = blockIdx.x * blockDim.x + threadIdx.x;
    if (bc == 0) g_nce = 0.0f;
    if (bc < B_ * C_) {
        const float* src = z + (size_t)bc * T_;
#pragma unroll
        for (int t = 0; t < T_; t++)
            g_enc[(size_t)t * B_ * C_ + bc] = src[t];
    }
}

// ---------------- pack A (c_t) into bf16 hi/lo tiles ------------------------
__global__ void convA_kernel(const float* __restrict__ A)
{
    int i  = blockIdx.x * 256 + threadIdx.x;        // float4 index
    int gr = i >> 10;                               // row 0..2047
    int k4 = (i & 1023) << 2;                       // k start
    float4 v = *(const float4*)(A + (size_t)gr * D_ + k4);
    float f[4] = {v.x, v.y, v.z, v.w};
    __nv_bfloat162 h0, h1, l0, l1;
    {
        __nv_bfloat16 hi[4], lo[4];
#pragma unroll
        for (int j = 0; j < 4; j++) {
            hi[j] = __float2bfloat16(f[j]);
            lo[j] = __float2bfloat16(f[j] - __bfloat162float(hi[j]));
        }
        h0.x = hi[0]; h0.y = hi[1]; h1.x = hi[2]; h1.y = hi[3];
        l0.x = lo[0]; l0.y = lo[1]; l1.x = lo[2]; l1.y = lo[3];
    }
    int rt = gr >> 7, row = gr & 127, kc = k4 >> 5, col = k4 & 31;
    size_t off = (((size_t)(rt * NC_ + kc) * 128) + row) * 32 + col;
    *(__nv_bfloat162*)(g_Ahi + off)     = h0;
    *(__nv_bfloat162*)(g_Ahi + off + 2) = h1;
    *(__nv_bfloat162*)(g_Alo + off)     = l0;
    *(__nv_bfloat162*)(g_Alo + off + 2) = l1;
}

// ---------------- pack W (Wk_w + pw1) into bf16 hi/lo tiles -----------------
__global__ void convW_kernel(const float* __restrict__ Wk_w,
                             const float* __restrict__ pw1)
{
    int i  = blockIdx.x * 256 + threadIdx.x;
    int rw = i >> 10;                               // 0..2431
    int k4 = (i & 1023) << 2;
    int t = rw >> 7, n = rw & 127;
    const float* src = (t < T_) ? (Wk_w + ((size_t)t * C_ + n) * D_ + k4)
                                : (pw1 + (size_t)n * D_ + k4);
    float4 v = *(const float4*)src;
    float f[4] = {v.x, v.y, v.z, v.w};
    __nv_bfloat162 h0, h1, l0, l1;
    {
        __nv_bfloat16 hi[4], lo[4];
#pragma unroll
        for (int j = 0; j < 4; j++) {
            hi[j] = __float2bfloat16(f[j]);
            lo[j] = __float2bfloat16(f[j] - __bfloat162float(hi[j]));
        }
        h0.x = hi[0]; h0.y = hi[1]; h1.x = hi[2]; h1.y = hi[3];
        l0.x = lo[0]; l0.y = lo[1]; l1.x = lo[2]; l1.y = lo[3];
    }
    int kc = k4 >> 5, col = k4 & 31;
    size_t off = (((size_t)(t * NC_ + kc) * 128) + n) * 32 + col;
    *(__nv_bfloat162*)(g_Whi + off)     = h0;
    *(__nv_bfloat162*)(g_Whi + off + 2) = h1;
    *(__nv_bfloat162*)(g_Wlo + off)     = l0;
    *(__nv_bfloat162*)(g_Wlo + off + 2) = l1;
}

// ---------------- mma.sync GEMM: C[128x128] per CTA, K=4096 ----------------
// grid (NT, 16). blockIdx.x = timestep (18 = pw1), blockIdx.y = 128-row tile.
// bf16 split: D += Ahi*Whi^T + Ahi*Wlo^T + Alo*Whi^T  (fp32 accum)
__global__ __launch_bounds__(256, 2) void gemm_mma_kernel(
    const float* __restrict__ Wk_b, const float* __restrict__ pb1)
{
    extern __shared__ __align__(128) char smem[];
    const uint32_t sb0 = smem_u32(smem);

    const int tid  = threadIdx.x;
    const int lane = tid & 31, wid = tid >> 5;
    const int wm = wid >> 2, wn = wid & 3;      // warp tile: 64 x 32
    const int tb = blockIdx.x, by = blockIdx.y;

    float acc[4][4][4];
#pragma unroll
    for (int mi = 0; mi < 4; mi++)
#pragma unroll
        for (int ni = 0; ni < 4; ni++)
#pragma unroll
            for (int q = 0; q < 4; q++) acc[mi][ni][q] = 0.0f;

    // cp.async thread mapping: 512 * 16B per tile, 2 per thread
    const int crow = tid >> 2;          // 0..63  (row pair base; second in j loop)
    const int cc16 = (tid & 3) << 4;    // byte offset 0,16,32,48

    // ldmatrix address components
    const int a_r  = wm * 64 + (lane & 15);
    const int a_kb = (lane >> 4) << 4;
    const int w_r  = wn * 32 + (lane & 7) + ((lane >> 4) << 3);
    const int w_kb = ((lane >> 3) & 1) << 4;

    // ---- prologue: chunk 0 -> stage 0 ----
    {
        size_t aoff = ((size_t)(by * NC_)) << 12;
        size_t woff = ((size_t)(tb * NC_)) << 12;
        const char* srcs[4] = {(const char*)(g_Ahi + aoff),
                               (const char*)(g_Alo + aoff),
                               (const char*)(g_Whi + woff),
                               (const char*)(g_Wlo + woff)};
#pragma unroll
        for (int t4 = 0; t4 < 4; t4++)
#pragma unroll
            for (int j = 0; j < 2; j++) {
                int row = crow + j * 64;
                cp16(sb0 + t4 * TILE_SM + row * AST_B + cc16,
                     srcs[t4] + row * 64 + cc16);
            }
        CP_COMMIT();
    }

    for (int kc = 0; kc < NC_; kc++) {
        if (kc + 1 < NC_) {
            uint32_t sb = sb0 + ((kc + 1) & 1) * STAGE_SM;
            size_t aoff = ((size_t)(by * NC_ + kc + 1)) << 12;
            size_t woff = ((size_t)(tb * NC_ + kc + 1)) << 12;
            const char* srcs[4] = {(const char*)(g_Ahi + aoff),
                                   (const char*)(g_Alo + aoff),
                                   (const char*)(g_Whi + woff),
                                   (const char*)(g_Wlo + woff)};
#pragma unroll
            for (int t4 = 0; t4 < 4; t4++)
#pragma unroll
                for (int j = 0; j < 2; j++) {
                    int row = crow + j * 64;
                    cp16(sb + t4 * TILE_SM + row * AST_B + cc16,
                         srcs[t4] + row * 64 + cc16);
                }
            CP_COMMIT();
            CP_WAIT(1);
        } else {
            CP_WAIT(0);
        }
        __syncthreads();

        const uint32_t st = sb0 + (kc & 1) * STAGE_SM;
        // products: (Ahi,Whi), (Ahi,Wlo), (Alo,Whi)
#pragma unroll
        for (int p = 0; p < 3; p++) {
            const uint32_t Ab = st + ((p == 2) ? TILE_SM : 0);
            const uint32_t Wb = st + ((p == 1) ? 3 : 2) * TILE_SM;
#pragma unroll
            for (int k16 = 0; k16 < 2; k16++) {
                uint32_t b[8];
                ldmx4(b,     Wb + (w_r)      * AST_B + k16 * 32 + w_kb);
                ldmx4(b + 4, Wb + (w_r + 16) * AST_B + k16 * 32 + w_kb);
#pragma unroll
                for (int mi = 0; mi < 4; mi++) {
                    uint32_t a[4];
                    ldmx4(a, Ab + (a_r + mi * 16) * AST_B + k16 * 32 + a_kb);
#pragma unroll
                    for (int ni = 0; ni < 4; ni++)
                        mma_bf16(acc[mi][ni], a, b + ni * 2);
                }
            }
        }
        __syncthreads();
    }

    // ---- epilogue: write C with bias ----
    const float* bias = (tb < T_) ? (Wk_b + tb * C_) : pb1;
    float* outp = (tb < T_) ? (g_pred + (size_t)tb * B_ * C_) : g_h;
    const int r0 = by * 128 + wm * 64 + (lane >> 2);
    const int c0 = wn * 32 + (lane & 3) * 2;
#pragma unroll
    for (int mi = 0; mi < 4; mi++) {
#pragma unroll
        for (int ni = 0; ni < 4; ni++) {
            int row = r0 + mi * 16;
            int col = c0 + ni * 8;
            float b0 = __ldg(bias + col), b1 = __ldg(bias + col + 1);
            float2 v;
            v.x = acc[mi][ni][0] + b0; v.y = acc[mi][ni][1] + b1;
            *(float2*)(outp + (size_t)row * C_ + col) = v;
            v.x = acc[mi][ni][2] + b0; v.y = acc[mi][ni][3] + b1;
            *(float2*)(outp + (size_t)(row + 8) * C_ + col) = v;
        }
    }
}

// ---------------- flash-style NCE: streaming logsumexp + diagonal ---------
#define FL_SMEM_FLOATS (128 * 132 + 16 * 132 + 128 * 17 + 3 * 128)

__global__ __launch_bounds__(256, 2) void flash_kernel()
{
    extern __shared__ float fsm[];
    float* Qs  = fsm;
    float* Ks  = Qs + 128 * 132;
    float* red = Ks + 16 * 132;
    float* m_s = red + 128 * 17;
    float* l_s = m_s + 128;
    float* d_s = l_s + 128;

    const int rb  = blockIdx.x;
    const int t   = blockIdx.y;
    const int tid = threadIdx.x;
    const int ty  = tid >> 4, tx = tid & 15;

    const float* enc_t  = g_enc  + ((size_t)t * B_ + rb * 128) * C_;
    const float* pred_t = g_pred + (size_t)t * B_ * C_;

    if (tid < 128) {
        m_s[tid] = -__int_as_float(0x7f800000);
        l_s[tid] = 0.0f;
        d_s[tid] = 0.0f;
    }

    for (int f = tid; f < 128 * 32; f += 256) {
        int r = f >> 5;
        int c = (f & 31) << 2;
        float4 v = *(const float4*)(enc_t + (size_t)r * C_ + c);
        Qs[(c + 0) * 132 + r] = v.x;
        Qs[(c + 1) * 132 + r] = v.y;
        Qs[(c + 2) * 132 + r] = v.z;
        Qs[(c + 3) * 132 + r] = v.w;
    }
    __syncthreads();

    for (int kt = 0; kt < 16; kt++) {
        float acc[8][8];
#pragma unroll
        for (int i = 0; i < 8; i++)
#pragma unroll
            for (int j = 0; j < 8; j++) acc[i][j] = 0.0f;

        const float* Kbase = pred_t + (size_t)kt * 128 * C_;
        for (int c0 = 0; c0 < 128; c0 += 16) {
#pragma unroll
            for (int i = 0; i < 2; i++) {
                int f  = tid + i * 256;
                int n  = f >> 2;
                int q4 = (f & 3) << 2;
                float4 v = *(const float4*)(Kbase + (size_t)n * C_ + c0 + q4);
                Ks[(q4 + 0) * 132 + n] = v.x;
                Ks[(q4 + 1) * 132 + n] = v.y;
                Ks[(q4 + 2) * 132 + n] = v.z;
                Ks[(q4 + 3) * 132 + n] = v.w;
            }
            __syncthreads();
#pragma unroll
            for (int kk = 0; kk < 16; kk++) {
                float a[8], b[8];
                *(float4*)(a)     = *(const float4*)&Qs[(c0 + kk) * 132 + ty * 8];
                *(float4*)(a + 4) = *(const float4*)&Qs[(c0 + kk) * 132 + ty * 8 + 4];
                *(float4*)(b)     = *(const float4*)&Ks[kk * 132 + tx * 8];
                *(float4*)(b + 4) = *(const float4*)&Ks[kk * 132 + tx * 8 + 4];
#pragma unroll
                for (int i = 0; i < 8; i++)
#pragma unroll
                    for (int j = 0; j < 8; j++)
                        acc[i][j] = fmaf(a[i], b[j], acc[i][j]);
            }
            __syncthreads();
        }

#pragma unroll
        for (int i = 0; i < 8; i++) {
            float m = acc[i][0];
#pragma unroll
            for (int j = 1; j < 8; j++) m = fmaxf(m, acc[i][j]);
            red[(ty * 8 + i) * 17 + tx] = m;
        }
        __syncthreads();
        if (tid < 128) {
            float tm = red[tid * 17];
#pragma unroll
            for (int x = 1; x < 16; x++) tm = fmaxf(tm, red[tid * 17 + x]);
            float mo = m_s[tid];
            float mn = fmaxf(mo, tm);
            l_s[tid] *= __expf(mo - mn);
            m_s[tid] = mn;
        }
        __syncthreads();
#pragma unroll
        for (int i = 0; i < 8; i++) {
            float mrow = m_s[ty * 8 + i];
            float s = 0.0f;
#pragma unroll
            for (int j = 0; j < 8; j++) s += __expf(acc[i][j] - mrow);
            red[(ty * 8 + i) * 17 + tx] = s;
        }
        if (kt == rb) {
#pragma unroll
            for (int i = 0; i < 8; i++) {
                int j = ty * 8 + i - tx * 8;
                if (j >= 0 && j < 8) d_s[ty * 8 + i] = acc[i][j];
            }
        }
        __syncthreads();
        if (tid < 128) {
            float s = 0.0f;
#pragma unroll
            for (int x = 0; x < 16; x++) s += red[tid * 17 + x];
            l_s[tid] += s;
        }
        __syncthreads();
    }

    float v = 0.0f;
    if (tid < 128) v = d_s[tid] - (m_s[tid] + logf(l_s[tid]));
#pragma unroll
    for (int o = 16; o > 0; o >>= 1) v += __shfl_down_sync(0xffffffffu, v, o);
    if ((tid & 31) == 0 && tid < 128) atomicAdd(&g_nce, v);
}

// ---------------- BatchNorm statistics -------------------------------------
__global__ void bnstat_kernel()
{
    const int c   = blockIdx.x;
    const int tid = threadIdx.x;
    float s = 0.0f, sq = 0.0f;
    for (int b = tid; b < B_; b += 256) {
        float v = g_h[(size_t)b * C_ + c];
        s += v;
        sq = fmaf(v, v, sq);
    }
    __shared__ float ss[256], sqq[256];
    ss[tid] = s; sqq[tid] = sq;
    __syncthreads();
    for (int st = 128; st > 0; st >>= 1) {
        if (tid < st) { ss[tid] += ss[tid + st]; sqq[tid] += sqq[tid + st]; }
        __syncthreads();
    }
    if (tid == 0) {
        float mean = ss[0] * (1.0f / B_);
        float var  = sqq[0] * (1.0f / B_) - mean * mean;
        g_mean[c] = mean;
        g_rstd[c] = rsqrtf(var + 1e-5f);
    }
}

// ---------------- projection head ------------------------------------------
__global__ void proj_kernel(const float* __restrict__ gamma,
                            const float* __restrict__ beta,
                            const float* __restrict__ pw2,
                            const float* __restrict__ pb2,
                            float* __restrict__ out)
{
    __shared__ float w2s[P_][132];
    __shared__ float hn[32][129];
    __shared__ float mg[C_], bg[C_];

    const int tid  = threadIdx.x;
    const int base = blockIdx.x * 32;

    for (int f = tid; f < P_ * C_; f += 256) {
        int p = f >> 7, c = f & 127;
        w2s[p][c] = pw2[f];
    }
    if (tid < C_) {
        float sc = g_rstd[tid] * gamma[tid];
        mg[tid] = sc;
        bg[tid] = beta[tid] - g_mean[tid] * sc;
    }
    __syncthreads();

    for (int f = tid; f < 32 * C_; f += 256) {
        int r = f >> 7, c = f & 127;
        float v = g_h[(size_t)(base + r) * C_ + c];
        v = v * mg[c] + bg[c];
        v = (v >= 0.0f) ? v : 0.01f * v;
        hn[r][c] = v;
    }
    __syncthreads();

    const int r  = tid >> 3;
    const int pg = (tid & 7) * 4;
    float accp[4];
#pragma unroll
    for (int p = 0; p < 4; p++) accp[p] = 0.0f;
    for (int c = 0; c < C_; c++) {
        float hv = hn[r][c];
#pragma unroll
        for (int p = 0; p < 4; p++)
            accp[p] = fmaf(hv, w2s[pg + p][c], accp[p]);
    }
#pragma unroll
    for (int p = 0; p < 4; p++)
        out[1 + (size_t)(base + r) * P_ + pg + p] = accp[p] + pb2[pg + p];

    if (blockIdx.x == 0 && tid == 0)
        out[0] = g_nce * (-1.0f / (float)(B_ * T_));
}

// ---------------- launch ---------------------------------------------------
extern "C" void kernel_launch(void* const* d_in, const int* in_sizes, int n_in,
                              void* d_out, int out_size)
{
    const float* z     = (const float*)d_in[0];
    const float* c_t   = (const float*)d_in[1];
    const float* Wk_w  = (const float*)d_in[2];
    const float* Wk_b  = (const float*)d_in[3];
    const float* pw1   = (const float*)d_in[4];
    const float* pb1   = (const float*)d_in[5];
    const float* gamma = (const float*)d_in[6];
    const float* beta  = (const float*)d_in[7];
    const float* pw2   = (const float*)d_in[8];
    const float* pb2   = (const float*)d_in[9];
    float* out = (float*)d_out;

    init_kernel<<<(B_ * C_ + 255) / 256, 256>>>(z);
    convA_kernel<<<(B_ * D_ / 4) / 256, 256>>>(c_t);
    convW_kernel<<<(NT * C_ * D_ / 4) / 256, 256>>>(Wk_w, pw1);

    cudaFuncSetAttribute(gemm_mma_kernel,
                         cudaFuncAttributeMaxDynamicSharedMemorySize, GEMM_SMEM);
    gemm_mma_kernel<<<dim3(NT, B_ / 128), 256, GEMM_SMEM>>>(Wk_b, pb1);

    size_t fl_smem = (size_t)FL_SMEM_FLOATS * sizeof(float);
    cudaFuncSetAttribute(flash_kernel,
                         cudaFuncAttributeMaxDynamicSharedMemorySize,
                         (int)fl_smem);
    flash_kernel<<<dim3(B_ / 128, T_), 256, fl_smem>>>();

    bnstat_kernel<<<C_, 256>>>();
    proj_kernel<<<B_ / 32, 256>>>(gamma, beta, pw2, pb2, out);
}

// round 5
// speedup vs baseline: 2.7914x; 1.6358x over previous
#include <cuda_runtime.h>
#include <cuda_bf16.h>
#include <cstdint>

#define B_ 2048
#define T_ 18
#define C_ 128
#define D_ 4096
#define P_ 32
#define NT 19               // 18 timesteps + pw1 block
#define NC_ (D_ / 32)       // 128 K-chunks of 32 bf16
#define AST_B 80            // gemm smem row stride (32 bf16 + 16B pad)
#define TILE_SM (128 * AST_B)
#define STAGE_SM (4 * TILE_SM)
#define GEMM_SMEM (2 * STAGE_SM)

// ---------------- scratch (device globals; no allocation allowed) ----------
__device__ float g_h   [B_ * C_];
__device__ float g_mean[C_];
__device__ float g_rstd[C_];
__device__ float g_nce;

// bf16 hi/lo GEMM operand tiles: [rowtile/t][kchunk][128 rows][32 cols]
__device__ __align__(16) __nv_bfloat16 g_Ahi[16 * NC_ * 4096];
__device__ __align__(16) __nv_bfloat16 g_Alo[16 * NC_ * 4096];
__device__ __align__(16) __nv_bfloat16 g_Whi[NT * NC_ * 4096];
__device__ __align__(16) __nv_bfloat16 g_Wlo[NT * NC_ * 4096];

// bf16 hi/lo enc + pred for flash: [t][b][c] row-major (C=128)
__device__ __align__(16) __nv_bfloat16 g_Ehi[T_ * B_ * C_];
__device__ __align__(16) __nv_bfloat16 g_Elo[T_ * B_ * C_];
__device__ __align__(16) __nv_bfloat16 g_Phi[T_ * B_ * C_];
__device__ __align__(16) __nv_bfloat16 g_Plo[T_ * B_ * C_];

// ---------------- helpers ---------------------------------------------------
__device__ __forceinline__ uint32_t smem_u32(const void* p) {
    uint32_t a;
    asm("{ .reg .u64 t; cvta.to.shared.u64 t, %1; cvt.u32.u64 %0, t; }"
        : "=r"(a) : "l"(p));
    return a;
}

__device__ __forceinline__ void cp16(uint32_t dst, const void* src) {
    asm volatile("cp.async.cg.shared.global [%0], [%1], 16;"
                 :: "r"(dst), "l"(src) : "memory");
}
#define CP_COMMIT() asm volatile("cp.async.commit_group;" ::: "memory")
#define CP_WAIT(N)  asm volatile("cp.async.wait_group %0;" :: "n"(N) : "memory")

__device__ __forceinline__ void ldmx4(uint32_t* r, uint32_t addr) {
    asm volatile("ldmatrix.sync.aligned.m8n8.x4.shared.b16 {%0,%1,%2,%3}, [%4];"
                 : "=r"(r[0]), "=r"(r[1]), "=r"(r[2]), "=r"(r[3]) : "r"(addr));
}

__device__ __forceinline__ void mma_bf16(float* c, const uint32_t* a,
                                         const uint32_t* b) {
    asm volatile(
        "mma.sync.aligned.m16n8k16.row.col.f32.bf16.bf16.f32 "
        "{%0,%1,%2,%3}, {%4,%5,%6,%7}, {%8,%9}, {%0,%1,%2,%3};"
        : "+f"(c[0]), "+f"(c[1]), "+f"(c[2]), "+f"(c[3])
        : "r"(a[0]), "r"(a[1]), "r"(a[2]), "r"(a[3]), "r"(b[0]), "r"(b[1]));
}

// ---------------- init: z_aug2 [B,C,T] -> Ehi/Elo [T,B,C]; zero nce --------
__global__ void init_kernel(const float* __restrict__ z)
{
    int bc = blockIdx.x * blockDim.x + threadIdx.x;
    if (bc == 0) g_nce = 0.0f;
    if (bc < B_ * C_) {
        const float* src = z + (size_t)bc * T_;
#pragma unroll
        for (int t = 0; t < T_; t++) {
            float v = src[t];
            __nv_bfloat16 hi = __float2bfloat16(v);
            __nv_bfloat16 lo = __float2bfloat16(v - __bfloat162float(hi));
            g_Ehi[(size_t)t * B_ * C_ + bc] = hi;
            g_Elo[(size_t)t * B_ * C_ + bc] = lo;
        }
    }
}

// ---------------- pack A (c_t) into bf16 hi/lo GEMM tiles -------------------
__global__ void convA_kernel(const float* __restrict__ A)
{
    int i  = blockIdx.x * 256 + threadIdx.x;
    int gr = i >> 10;
    int k4 = (i & 1023) << 2;
    float4 v = *(const float4*)(A + (size_t)gr * D_ + k4);
    float f[4] = {v.x, v.y, v.z, v.w};
    __nv_bfloat162 h0, h1, l0, l1;
    {
        __nv_bfloat16 hi[4], lo[4];
#pragma unroll
        for (int j = 0; j < 4; j++) {
            hi[j] = __float2bfloat16(f[j]);
            lo[j] = __float2bfloat16(f[j] - __bfloat162float(hi[j]));
        }
        h0.x = hi[0]; h0.y = hi[1]; h1.x = hi[2]; h1.y = hi[3];
        l0.x = lo[0]; l0.y = lo[1]; l1.x = lo[2]; l1.y = lo[3];
    }
    int rt = gr >> 7, row = gr & 127, kc = k4 >> 5, col = k4 & 31;
    size_t off = (((size_t)(rt * NC_ + kc) * 128) + row) * 32 + col;
    *(__nv_bfloat162*)(g_Ahi + off)     = h0;
    *(__nv_bfloat162*)(g_Ahi + off + 2) = h1;
    *(__nv_bfloat162*)(g_Alo + off)     = l0;
    *(__nv_bfloat162*)(g_Alo + off + 2) = l1;
}

// ---------------- pack W (Wk_w + pw1) into bf16 hi/lo GEMM tiles ------------
__global__ void convW_kernel(const float* __restrict__ Wk_w,
                             const float* __restrict__ pw1)
{
    int i  = blockIdx.x * 256 + threadIdx.x;
    int rw = i >> 10;
    int k4 = (i & 1023) << 2;
    int t = rw >> 7, n = rw & 127;
    const float* src = (t < T_) ? (Wk_w + ((size_t)t * C_ + n) * D_ + k4)
                                : (pw1 + (size_t)n * D_ + k4);
    float4 v = *(const float4*)src;
    float f[4] = {v.x, v.y, v.z, v.w};
    __nv_bfloat162 h0, h1, l0, l1;
    {
        __nv_bfloat16 hi[4], lo[4];
#pragma unroll
        for (int j = 0; j < 4; j++) {
            hi[j] = __float2bfloat16(f[j]);
            lo[j] = __float2bfloat16(f[j] - __bfloat162float(hi[j]));
        }
        h0.x = hi[0]; h0.y = hi[1]; h1.x = hi[2]; h1.y = hi[3];
        l0.x = lo[0]; l0.y = lo[1]; l1.x = lo[2]; l1.y = lo[3];
    }
    int kc = k4 >> 5, col = k4 & 31;
    size_t off = (((size_t)(t * NC_ + kc) * 128) + n) * 32 + col;
    *(__nv_bfloat162*)(g_Whi + off)     = h0;
    *(__nv_bfloat162*)(g_Whi + off + 2) = h1;
    *(__nv_bfloat162*)(g_Wlo + off)     = l0;
    *(__nv_bfloat162*)(g_Wlo + off + 2) = l1;
}

// ---------------- mma.sync GEMM: C[128x128] per CTA, K=4096 ----------------
// bf16 split: D += Ahi*Whi^T + Ahi*Wlo^T + Alo*Whi^T  (fp32 accum)
// Epilogue: t<18 -> pred as bf16 hi/lo; t==18 -> g_h fp32.
__global__ __launch_bounds__(256, 2) void gemm_mma_kernel(
    const float* __restrict__ Wk_b, const float* __restrict__ pb1)
{
    extern __shared__ __align__(128) char smem[];
    const uint32_t sb0 = smem_u32(smem);

    const int tid  = threadIdx.x;
    const int lane = tid & 31, wid = tid >> 5;
    const int wm = wid >> 2, wn = wid & 3;      // warp tile: 64 x 32
    const int tb = blockIdx.x, by = blockIdx.y;

    float acc[4][4][4];
#pragma unroll
    for (int mi = 0; mi < 4; mi++)
#pragma unroll
        for (int ni = 0; ni < 4; ni++)
#pragma unroll
            for (int q = 0; q < 4; q++) acc[mi][ni][q] = 0.0f;

    const int crow = tid >> 2;
    const int cc16 = (tid & 3) << 4;

    const int a_r  = wm * 64 + (lane & 15);
    const int a_kb = (lane >> 4) << 4;
    const int w_r  = wn * 32 + (lane & 7) + ((lane >> 4) << 3);
    const int w_kb = ((lane >> 3) & 1) << 4;

    {   // prologue: chunk 0 -> stage 0
        size_t aoff = ((size_t)(by * NC_)) << 12;
        size_t woff = ((size_t)(tb * NC_)) << 12;
        const char* srcs[4] = {(const char*)(g_Ahi + aoff),
                               (const char*)(g_Alo + aoff),
                               (const char*)(g_Whi + woff),
                               (const char*)(g_Wlo + woff)};
#pragma unroll
        for (int t4 = 0; t4 < 4; t4++)
#pragma unroll
            for (int j = 0; j < 2; j++) {
                int row = crow + j * 64;
                cp16(sb0 + t4 * TILE_SM + row * AST_B + cc16,
                     srcs[t4] + row * 64 + cc16);
            }
        CP_COMMIT();
    }

    for (int kc = 0; kc < NC_; kc++) {
        if (kc + 1 < NC_) {
            uint32_t sb = sb0 + ((kc + 1) & 1) * STAGE_SM;
            size_t aoff = ((size_t)(by * NC_ + kc + 1)) << 12;
            size_t woff = ((size_t)(tb * NC_ + kc + 1)) << 12;
            const char* srcs[4] = {(const char*)(g_Ahi + aoff),
                                   (const char*)(g_Alo + aoff),
                                   (const char*)(g_Whi + woff),
                                   (const char*)(g_Wlo + woff)};
#pragma unroll
            for (int t4 = 0; t4 < 4; t4++)
#pragma unroll
                for (int j = 0; j < 2; j++) {
                    int row = crow + j * 64;
                    cp16(sb + t4 * TILE_SM + row * AST_B + cc16,
                         srcs[t4] + row * 64 + cc16);
                }
            CP_COMMIT();
            CP_WAIT(1);
        } else {
            CP_WAIT(0);
        }
        __syncthreads();

        const uint32_t st = sb0 + (kc & 1) * STAGE_SM;
        const uint32_t Ahi_b = st, Alo_b = st + TILE_SM;
        const uint32_t Whi_b = st + 2 * TILE_SM, Wlo_b = st + 3 * TILE_SM;
#pragma unroll
        for (int k16 = 0; k16 < 2; k16++) {
            uint32_t bh[8], bl[8];
            ldmx4(bh,     Whi_b + (w_r)      * AST_B + k16 * 32 + w_kb);
            ldmx4(bh + 4, Whi_b + (w_r + 16) * AST_B + k16 * 32 + w_kb);
            ldmx4(bl,     Wlo_b + (w_r)      * AST_B + k16 * 32 + w_kb);
            ldmx4(bl + 4, Wlo_b + (w_r + 16) * AST_B + k16 * 32 + w_kb);
#pragma unroll
            for (int mi = 0; mi < 4; mi++) {
                uint32_t a[4];
                ldmx4(a, Ahi_b + (a_r + mi * 16) * AST_B + k16 * 32 + a_kb);
#pragma unroll
                for (int ni = 0; ni < 4; ni++) mma_bf16(acc[mi][ni], a, bh + ni * 2);
#pragma unroll
                for (int ni = 0; ni < 4; ni++) mma_bf16(acc[mi][ni], a, bl + ni * 2);
            }
#pragma unroll
            for (int mi = 0; mi < 4; mi++) {
                uint32_t a[4];
                ldmx4(a, Alo_b + (a_r + mi * 16) * AST_B + k16 * 32 + a_kb);
#pragma unroll
                for (int ni = 0; ni < 4; ni++) mma_bf16(acc[mi][ni], a, bh + ni * 2);
            }
        }
        __syncthreads();
    }

    // ---- epilogue ----
    const int r0 = by * 128 + wm * 64 + (lane >> 2);
    const int c0 = wn * 32 + (lane & 3) * 2;
    if (tb < T_) {
        const float* bias = Wk_b + tb * C_;
        __nv_bfloat16* ph = g_Phi + (size_t)tb * B_ * C_;
        __nv_bfloat16* pl = g_Plo + (size_t)tb * B_ * C_;
#pragma unroll
        for (int mi = 0; mi < 4; mi++)
#pragma unroll
            for (int ni = 0; ni < 4; ni++) {
                int row = r0 + mi * 16, col = c0 + ni * 8;
                float b0 = __ldg(bias + col), b1 = __ldg(bias + col + 1);
#pragma unroll
                for (int h = 0; h < 2; h++) {
                    float v0 = acc[mi][ni][h * 2]     + b0;
                    float v1 = acc[mi][ni][h * 2 + 1] + b1;
                    __nv_bfloat162 hh, ll;
                    hh.x = __float2bfloat16(v0);
                    ll.x = __float2bfloat16(v0 - __bfloat162float(hh.x));
                    hh.y = __float2bfloat16(v1);
                    ll.y = __float2bfloat16(v1 - __bfloat162float(hh.y));
                    size_t off = (size_t)(row + h * 8) * C_ + col;
                    *(__nv_bfloat162*)(ph + off) = hh;
                    *(__nv_bfloat162*)(pl + off) = ll;
                }
            }
    } else {
        const float* bias = pb1;
#pragma unroll
        for (int mi = 0; mi < 4; mi++)
#pragma unroll
            for (int ni = 0; ni < 4; ni++) {
                int row = r0 + mi * 16, col = c0 + ni * 8;
                float b0 = __ldg(bias + col), b1 = __ldg(bias + col + 1);
                float2 v;
                v.x = acc[mi][ni][0] + b0; v.y = acc[mi][ni][1] + b1;
                *(float2*)(g_h + (size_t)row * C_ + col) = v;
                v.x = acc[mi][ni][2] + b0; v.y = acc[mi][ni][3] + b1;
                *(float2*)(g_h + (size_t)(row + 8) * C_ + col) = v;
            }
    }
}

// ---------------- flash NCE via mma.sync: block = 128 q-rows x t -----------
#define FST 272                     // 128 bf16 + 16B pad
#define FTILE_ (128 * FST)          // 34816
#define FL_REDM (6 * FTILE_)
#define FL_REDL (FL_REDM + 1024)
#define FL_DIAG (FL_REDL + 1024)
#define FL_SMEM (FL_DIAG + 512)     // 211456 bytes

__global__ __launch_bounds__(256, 1) void flash_mma_kernel()
{
    extern __shared__ __align__(128) char smem[];
    const uint32_t sb = smem_u32(smem);
    float* red_m = (float*)(smem + FL_REDM);
    float* red_l = (float*)(smem + FL_REDL);
    float* diag  = (float*)(smem + FL_DIAG);

    const int rb = blockIdx.x, t = blockIdx.y;
    const int tid = threadIdx.x, lane = tid & 31, wid = tid >> 5;
    const int wm = wid >> 1, wn = wid & 1;      // warp tile 32 x 64

    const __nv_bfloat16* Ehi = g_Ehi + ((size_t)t * B_ + rb * 128) * C_;
    const __nv_bfloat16* Elo = g_Elo + ((size_t)t * B_ + rb * 128) * C_;
    const __nv_bfloat16* Phi = g_Phi + (size_t)t * B_ * C_;
    const __nv_bfloat16* Plo = g_Plo + (size_t)t * B_ * C_;

    // ---- load Q (hi+lo) ----
#pragma unroll
    for (int f = 0; f < 8; f++) {
        int id = tid + f * 256, r = id >> 4, ch = (id & 15) << 4;
        cp16(sb + r * FST + ch,          (const char*)Ehi + r * 256 + ch);
        cp16(sb + FTILE_ + r * FST + ch, (const char*)Elo + r * 256 + ch);
    }
    CP_COMMIT();
    // ---- load K stage 0 ----
#pragma unroll
    for (int f = 0; f < 8; f++) {
        int id = tid + f * 256, r = id >> 4, ch = (id & 15) << 4;
        cp16(sb + 2 * FTILE_ + r * FST + ch, (const char*)Phi + r * 256 + ch);
        cp16(sb + 3 * FTILE_ + r * FST + ch, (const char*)Plo + r * 256 + ch);
    }
    CP_COMMIT();

    // per-thread online-softmax state, 4 rows: idx = mi*2 + h
    float m_r[4], l_r[4];
#pragma unroll
    for (int r = 0; r < 4; r++) { m_r[r] = -3.0e38f; l_r[r] = 0.0f; }

    const int a_rr = wm * 32 + (lane & 15);
    const int a_kb = (lane >> 4) << 4;
    const int b_rr = wn * 64 + (lane & 7) + ((lane >> 4) << 3);
    const int b_kb = ((lane >> 3) & 1) << 4;
    const int row4 = lane >> 2;              // row within m16 half

    for (int kt = 0; kt < 16; kt++) {
        if (kt + 1 < 16) {
            uint32_t kb = sb + (2 + ((kt + 1) & 1) * 2) * FTILE_;
            const char* sh = (const char*)Phi + (size_t)(kt + 1) * 128 * 256;
            const char* sl = (const char*)Plo + (size_t)(kt + 1) * 128 * 256;
#pragma unroll
            for (int f = 0; f < 8; f++) {
                int id = tid + f * 256, r = id >> 4, ch = (id & 15) << 4;
                cp16(kb + r * FST + ch,          sh + r * 256 + ch);
                cp16(kb + FTILE_ + r * FST + ch, sl + r * 256 + ch);
            }
            CP_COMMIT();
            CP_WAIT(1);
        } else {
            CP_WAIT(0);
        }
        __syncthreads();

        const uint32_t Qh = sb, Ql = sb + FTILE_;
        const uint32_t Kh = sb + (2 + (kt & 1) * 2) * FTILE_;
        const uint32_t Kl = Kh + FTILE_;

        float acc[2][8][4];
#pragma unroll
        for (int mi = 0; mi < 2; mi++)
#pragma unroll
            for (int ni = 0; ni < 8; ni++)
#pragma unroll
                for (int q = 0; q < 4; q++) acc[mi][ni][q] = 0.0f;

#pragma unroll
        for (int k16 = 0; k16 < 8; k16++) {
            uint32_t bh[16], bl[16];
#pragma unroll
            for (int g = 0; g < 4; g++) {
                ldmx4(bh + g * 4, Kh + (b_rr + g * 16) * FST + k16 * 32 + b_kb);
                ldmx4(bl + g * 4, Kl + (b_rr + g * 16) * FST + k16 * 32 + b_kb);
            }
#pragma unroll
            for (int mi = 0; mi < 2; mi++) {
                uint32_t a[4];
                ldmx4(a, Qh + (a_rr + mi * 16) * FST + k16 * 32 + a_kb);
#pragma unroll
                for (int ni = 0; ni < 8; ni++) mma_bf16(acc[mi][ni], a, bh + ni * 2);
#pragma unroll
                for (int ni = 0; ni < 8; ni++) mma_bf16(acc[mi][ni], a, bl + ni * 2);
            }
#pragma unroll
            for (int mi = 0; mi < 2; mi++) {
                uint32_t a[4];
                ldmx4(a, Ql + (a_rr + mi * 16) * FST + k16 * 32 + a_kb);
#pragma unroll
                for (int ni = 0; ni < 8; ni++) mma_bf16(acc[mi][ni], a, bh + ni * 2);
            }
        }

        // ---- online softmax on fragments ----
        float rmax[4];
#pragma unroll
        for (int mi = 0; mi < 2; mi++)
#pragma unroll
            for (int h = 0; h < 2; h++) {
                float m = acc[mi][0][h * 2];
#pragma unroll
                for (int ni = 0; ni < 8; ni++) {
                    m = fmaxf(m, acc[mi][ni][h * 2]);
                    m = fmaxf(m, acc[mi][ni][h * 2 + 1]);
                }
                rmax[mi * 2 + h] = m;
            }
#pragma unroll
        for (int r = 0; r < 4; r++) {
            rmax[r] = fmaxf(rmax[r], __shfl_xor_sync(0xffffffffu, rmax[r], 1));
            rmax[r] = fmaxf(rmax[r], __shfl_xor_sync(0xffffffffu, rmax[r], 2));
        }
        if ((lane & 3) == 0) {
#pragma unroll
            for (int r = 0; r < 4; r++) {
                int rg = wm * 32 + (r >> 1) * 16 + row4 + (r & 1) * 8;
                red_m[rg * 2 + wn] = rmax[r];
            }
        }
        __syncthreads();

        float m_new[4], s_r[4];
#pragma unroll
        for (int r = 0; r < 4; r++) {
            int rg = wm * 32 + (r >> 1) * 16 + row4 + (r & 1) * 8;
            float tm = fmaxf(red_m[rg * 2], red_m[rg * 2 + 1]);
            m_new[r] = fmaxf(m_r[r], tm);
        }
#pragma unroll
        for (int mi = 0; mi < 2; mi++)
#pragma unroll
            for (int h = 0; h < 2; h++) {
                float mn = m_new[mi * 2 + h];
                float s = 0.0f;
#pragma unroll
                for (int ni = 0; ni < 8; ni++) {
                    s += __expf(acc[mi][ni][h * 2] - mn);
                    s += __expf(acc[mi][ni][h * 2 + 1] - mn);
                }
                s_r[mi * 2 + h] = s;
            }
#pragma unroll
        for (int r = 0; r < 4; r++) {
            s_r[r] += __shfl_xor_sync(0xffffffffu, s_r[r], 1);
            s_r[r] += __shfl_xor_sync(0xffffffffu, s_r[r], 2);
        }
        if ((lane & 3) == 0) {
#pragma unroll
            for (int r = 0; r < 4; r++) {
                int rg = wm * 32 + (r >> 1) * 16 + row4 + (r & 1) * 8;
                red_l[rg * 2 + wn] = s_r[r];
            }
        }
        if (kt == rb) {     // diagonal capture (raw logits)
#pragma unroll
            for (int mi = 0; mi < 2; mi++)
#pragma unroll
                for (int ni = 0; ni < 8; ni++)
#pragma unroll
                    for (int q = 0; q < 4; q++) {
                        int rl = wm * 32 + mi * 16 + row4 + (q >> 1) * 8;
                        int cl = wn * 64 + ni * 8 + (lane & 3) * 2 + (q & 1);
                        if (rl == cl) diag[rl] = acc[mi][ni][q];
                    }
        }
        __syncthreads();
#pragma unroll
        for (int r = 0; r < 4; r++) {
            int rg = wm * 32 + (r >> 1) * 16 + row4 + (r & 1) * 8;
            float ts = red_l[rg * 2] + red_l[rg * 2 + 1];
            l_r[r] = l_r[r] * __expf(m_r[r] - m_new[r]) + ts;
            m_r[r] = m_new[r];
        }
    }

    // ---- per-row nce contributions ----
    if (wn == 0 && (lane & 3) == 0) {
        float v = 0.0f;
#pragma unroll
        for (int r = 0; r < 4; r++) {
            int rg = wm * 32 + (r >> 1) * 16 + row4 + (r & 1) * 8;
            v += diag[rg] - (m_r[r] + logf(l_r[r]));
        }
        atomicAdd(&g_nce, v);
    }
}

// ---------------- BatchNorm statistics -------------------------------------
__global__ void bnstat_kernel()
{
    const int c   = blockIdx.x;
    const int tid = threadIdx.x;
    float s = 0.0f, sq = 0.0f;
    for (int b = tid; b < B_; b += 256) {
        float v = g_h[(size_t)b * C_ + c];
        s += v;
        sq = fmaf(v, v, sq);
    }
    __shared__ float ss[256], sqq[256];
    ss[tid] = s; sqq[tid] = sq;
    __syncthreads();
    for (int st = 128; st > 0; st >>= 1) {
        if (tid < st) { ss[tid] += ss[tid + st]; sqq[tid] += sqq[tid + st]; }
        __syncthreads();
    }
    if (tid == 0) {
        float mean = ss[0] * (1.0f / B_);
        float var  = sqq[0] * (1.0f / B_) - mean * mean;
        g_mean[c] = mean;
        g_rstd[c] = rsqrtf(var + 1e-5f);
    }
}

// ---------------- projection head ------------------------------------------
__global__ void proj_kernel(const float* __restrict__ gamma,
                            const float* __restrict__ beta,
                            const float* __restrict__ pw2,
                            const float* __restrict__ pb2,
                            float* __restrict__ out)
{
    __shared__ float w2s[P_][132];
    __shared__ float hn[32][129];
    __shared__ float mg[C_], bg[C_];

    const int tid  = threadIdx.x;
    const int base = blockIdx.x * 32;

    for (int f = tid; f < P_ * C_; f += 256) {
        int p = f >> 7, c = f & 127;
        w2s[p][c] = pw2[f];
    }
    if (tid < C_) {
        float sc = g_rstd[tid] * gamma[tid];
        mg[tid] = sc;
        bg[tid] = beta[tid] - g_mean[tid] * sc;
    }
    __syncthreads();

    for (int f = tid; f < 32 * C_; f += 256) {
        int r = f >> 7, c = f & 127;
        float v = g_h[(size_t)(base + r) * C_ + c];
        v = v * mg[c] + bg[c];
        v = (v >= 0.0f) ? v : 0.01f * v;
        hn[r][c] = v;
    }
    __syncthreads();

    const int r  = tid >> 3;
    const int pg = (tid & 7) * 4;
    float accp[4];
#pragma unroll
    for (int p = 0; p < 4; p++) accp[p] = 0.0f;
    for (int c = 0; c < C_; c++) {
        float hv = hn[r][c];
#pragma unroll
        for (int p = 0; p < 4; p++)
            accp[p] = fmaf(hv, w2s[pg + p][c], accp[p]);
    }
#pragma unroll
    for (int p = 0; p < 4; p++)
        out[1 + (size_t)(base + r) * P_ + pg + p] = accp[p] + pb2[pg + p];

    if (blockIdx.x == 0 && tid == 0)
        out[0] = g_nce * (-1.0f / (float)(B_ * T_));
}

// ---------------- launch ---------------------------------------------------
extern "C" void kernel_launch(void* const* d_in, const int* in_sizes, int n_in,
                              void* d_out, int out_size)
{
    const float* z     = (const float*)d_in[0];
    const float* c_t   = (const float*)d_in[1];
    const float* Wk_w  = (const float*)d_in[2];
    const float* Wk_b  = (const float*)d_in[3];
    const float* pw1   = (const float*)d_in[4];
    const float* pb1   = (const float*)d_in[5];
    const float* gamma = (const float*)d_in[6];
    const float* beta  = (const float*)d_in[7];
    const float* pw2   = (const float*)d_in[8];
    const float* pb2   = (const float*)d_in[9];
    float* out = (float*)d_out;

    init_kernel<<<(B_ * C_ + 255) / 256, 256>>>(z);
    convA_kernel<<<(B_ * D_ / 4) / 256, 256>>>(c_t);
    convW_kernel<<<(NT * C_ * D_ / 4) / 256, 256>>>(Wk_w, pw1);

    cudaFuncSetAttribute(gemm_mma_kernel,
                         cudaFuncAttributeMaxDynamicSharedMemorySize, GEMM_SMEM);
    gemm_mma_kernel<<<dim3(NT, B_ / 128), 256, GEMM_SMEM>>>(Wk_b, pb1);

    cudaFuncSetAttribute(flash_mma_kernel,
                         cudaFuncAttributeMaxDynamicSharedMemorySize, FL_SMEM);
    flash_mma_kernel<<<dim3(B_ / 128, T_), 256, FL_SMEM>>>();

    bnstat_kernel<<<C_, 256>>>();
    proj_kernel<<<B_ / 32, 256>>>(gamma, beta, pw2, pb2, out);
}

// round 6
// speedup vs baseline: 2.9471x; 1.0558x over previous
#include <cuda_runtime.h>
#include <cuda_bf16.h>
#include <cstdint>

#define B_ 2048
#define T_ 18
#define C_ 128
#define D_ 4096
#define P_ 32
#define NT 19               // 18 timesteps + pw1 block
#define NC_ (D_ / 32)       // 128 K-chunks of 32 bf16
#define AST_B 80            // gemm smem row stride (32 bf16 + 16B pad)
#define TILE_A (128 * AST_B)        // 10240
#define TILE_W (64 * AST_B)         // 5120
#define STAGE_SM (2 * TILE_A + 2 * TILE_W)   // 30720
#define GEMM_SMEM (2 * STAGE_SM)             // 61440

// ---------------- scratch (device globals; no allocation allowed) ----------
__device__ float g_h   [B_ * C_];
__device__ float g_mean[C_];
__device__ float g_rstd[C_];
__device__ float g_nce;

// bf16 hi/lo GEMM operand tiles: [rowtile/t][kchunk][128 rows][32 cols]
__device__ __align__(16) __nv_bfloat16 g_Ahi[16 * NC_ * 4096];
__device__ __align__(16) __nv_bfloat16 g_Alo[16 * NC_ * 4096];
__device__ __align__(16) __nv_bfloat16 g_Whi[NT * NC_ * 4096];
__device__ __align__(16) __nv_bfloat16 g_Wlo[NT * NC_ * 4096];

// bf16 hi/lo enc + pred for flash: [t][b][c] row-major (C=128)
__device__ __align__(16) __nv_bfloat16 g_Ehi[T_ * B_ * C_];
__device__ __align__(16) __nv_bfloat16 g_Elo[T_ * B_ * C_];
__device__ __align__(16) __nv_bfloat16 g_Phi[T_ * B_ * C_];
__device__ __align__(16) __nv_bfloat16 g_Plo[T_ * B_ * C_];

// ---------------- helpers ---------------------------------------------------
__device__ __forceinline__ uint32_t smem_u32(const void* p) {
    uint32_t a;
    asm("{ .reg .u64 t; cvta.to.shared.u64 t, %1; cvt.u32.u64 %0, t; }"
        : "=r"(a) : "l"(p));
    return a;
}

__device__ __forceinline__ void cp16(uint32_t dst, const void* src) {
    asm volatile("cp.async.cg.shared.global [%0], [%1], 16;"
                 :: "r"(dst), "l"(src) : "memory");
}
#define CP_COMMIT() asm volatile("cp.async.commit_group;" ::: "memory")
#define CP_WAIT(N)  asm volatile("cp.async.wait_group %0;" :: "n"(N) : "memory")

__device__ __forceinline__ void ldmx4(uint32_t* r, uint32_t addr) {
    asm volatile("ldmatrix.sync.aligned.m8n8.x4.shared.b16 {%0,%1,%2,%3}, [%4];"
                 : "=r"(r[0]), "=r"(r[1]), "=r"(r[2]), "=r"(r[3]) : "r"(addr));
}

__device__ __forceinline__ void mma_bf16(float* c, const uint32_t* a,
                                         const uint32_t* b) {
    asm volatile(
        "mma.sync.aligned.m16n8k16.row.col.f32.bf16.bf16.f32 "
        "{%0,%1,%2,%3}, {%4,%5,%6,%7}, {%8,%9}, {%0,%1,%2,%3};"
        : "+f"(c[0]), "+f"(c[1]), "+f"(c[2]), "+f"(c[3])
        : "r"(a[0]), "r"(a[1]), "r"(a[2]), "r"(a[3]), "r"(b[0]), "r"(b[1]));
}

// ---------------- init: z_aug2 [B,C,T] -> Ehi/Elo [T,B,C]; zero nce --------
__global__ void init_kernel(const float* __restrict__ z)
{
    int bc = blockIdx.x * blockDim.x + threadIdx.x;
    if (bc == 0) g_nce = 0.0f;
    if (bc < B_ * C_) {
        const float* src = z + (size_t)bc * T_;
#pragma unroll
        for (int t = 0; t < T_; t++) {
            float v = src[t];
            __nv_bfloat16 hi = __float2bfloat16(v);
            __nv_bfloat16 lo = __float2bfloat16(v - __bfloat162float(hi));
            g_Ehi[(size_t)t * B_ * C_ + bc] = hi;
            g_Elo[(size_t)t * B_ * C_ + bc] = lo;
        }
    }
}

// ---------------- pack A (c_t) into bf16 hi/lo GEMM tiles -------------------
__global__ void convA_kernel(const float* __restrict__ A)
{
    int i  = blockIdx.x * 256 + threadIdx.x;
    int gr = i >> 10;
    int k4 = (i & 1023) << 2;
    float4 v = *(const float4*)(A + (size_t)gr * D_ + k4);
    float f[4] = {v.x, v.y, v.z, v.w};
    __nv_bfloat162 h0, h1, l0, l1;
    {
        __nv_bfloat16 hi[4], lo[4];
#pragma unroll
        for (int j = 0; j < 4; j++) {
            hi[j] = __float2bfloat16(f[j]);
            lo[j] = __float2bfloat16(f[j] - __bfloat162float(hi[j]));
        }
        h0.x = hi[0]; h0.y = hi[1]; h1.x = hi[2]; h1.y = hi[3];
        l0.x = lo[0]; l0.y = lo[1]; l1.x = lo[2]; l1.y = lo[3];
    }
    int rt = gr >> 7, row = gr & 127, kc = k4 >> 5, col = k4 & 31;
    size_t off = (((size_t)(rt * NC_ + kc) * 128) + row) * 32 + col;
    *(__nv_bfloat162*)(g_Ahi + off)     = h0;
    *(__nv_bfloat162*)(g_Ahi + off + 2) = h1;
    *(__nv_bfloat162*)(g_Alo + off)     = l0;
    *(__nv_bfloat162*)(g_Alo + off + 2) = l1;
}

// ---------------- pack W (Wk_w + pw1) into bf16 hi/lo GEMM tiles ------------
__global__ void convW_kernel(const float* __restrict__ Wk_w,
                             const float* __restrict__ pw1)
{
    int i  = blockIdx.x * 256 + threadIdx.x;
    int rw = i >> 10;
    int k4 = (i & 1023) << 2;
    int t = rw >> 7, n = rw & 127;
    const float* src = (t < T_) ? (Wk_w + ((size_t)t * C_ + n) * D_ + k4)
                                : (pw1 + (size_t)n * D_ + k4);
    float4 v = *(const float4*)src;
    float f[4] = {v.x, v.y, v.z, v.w};
    __nv_bfloat162 h0, h1, l0, l1;
    {
        __nv_bfloat16 hi[4], lo[4];
#pragma unroll
        for (int j = 0; j < 4; j++) {
            hi[j] = __float2bfloat16(f[j]);
            lo[j] = __float2bfloat16(f[j] - __bfloat162float(hi[j]));
        }
        h0.x = hi[0]; h0.y = hi[1]; h1.x = hi[2]; h1.y = hi[3];
        l0.x = lo[0]; l0.y = lo[1]; l1.x = lo[2]; l1.y = lo[3];
    }
    int kc = k4 >> 5, col = k4 & 31;
    size_t off = (((size_t)(t * NC_ + kc) * 128) + n) * 32 + col;
    *(__nv_bfloat162*)(g_Whi + off)     = h0;
    *(__nv_bfloat162*)(g_Whi + off + 2) = h1;
    *(__nv_bfloat162*)(g_Wlo + off)     = l0;
    *(__nv_bfloat162*)(g_Wlo + off + 2) = l1;
}

// ---------------- mma.sync GEMM: C[128x64] per CTA, K=4096 -----------------
// grid (NT, 32): blockIdx.y -> rowtile = by>>1 (128 rows), nh = by&1 (64 cols)
// bf16 split: D += Ahi*Whi^T + Ahi*Wlo^T + Alo*Whi^T  (fp32 accum)
// warp tile 32x32: wm = wid>>1 (0..3), wn = wid&1 (0..1)
__global__ __launch_bounds__(256, 3) void gemm_mma_kernel(
    const float* __restrict__ Wk_b, const float* __restrict__ pb1)
{
    extern __shared__ __align__(128) char smem[];
    const uint32_t sb0 = smem_u32(smem);

    const int tid  = threadIdx.x;
    const int lane = tid & 31, wid = tid >> 5;
    const int wm = wid >> 1, wn = wid & 1;
    const int tb = blockIdx.x;
    const int rt = blockIdx.y >> 1;       // row tile 0..15
    const int nh = blockIdx.y & 1;        // N half 0..1

    float acc[2][4][4];
#pragma unroll
    for (int mi = 0; mi < 2; mi++)
#pragma unroll
        for (int ni = 0; ni < 4; ni++)
#pragma unroll
            for (int q = 0; q < 4; q++) acc[mi][ni][q] = 0.0f;

    const int a_r  = wm * 32 + (lane & 15);
    const int a_kb = (lane >> 4) << 4;
    const int w_r  = wn * 32 + (lane & 7) + ((lane >> 4) << 3);
    const int w_kb = ((lane >> 3) & 1) << 4;

    // cp.async mapping (per stage): A = 1024 x16B (2 tiles), W = 512 x16B
    const int a_u_r  = tid >> 2;          // 0..63 (+64,+128.. via loop)
    const int u_c16  = (tid & 3) << 4;

#define GEMM_LOADS(stage_base, kcL)                                           \
    do {                                                                      \
        const char* As[2] = {                                                 \
            (const char*)(g_Ahi + (((size_t)(rt * NC_ + (kcL))) << 12)),      \
            (const char*)(g_Alo + (((size_t)(rt * NC_ + (kcL))) << 12))};     \
        const char* Ws[2] = {                                                 \
            (const char*)(g_Whi + (((size_t)(tb * NC_ + (kcL))) << 12))       \
                + nh * 4096,                                                  \
            (const char*)(g_Wlo + (((size_t)(tb * NC_ + (kcL))) << 12))       \
                + nh * 4096};                                                 \
        _Pragma("unroll")                                                     \
        for (int t2 = 0; t2 < 2; t2++)                                        \
            _Pragma("unroll")                                                 \
            for (int j = 0; j < 2; j++) {                                     \
                int row = a_u_r + j * 64;                                     \
                cp16((stage_base) + t2 * TILE_A + row * AST_B + u_c16,        \
                     As[t2] + row * 64 + u_c16);                              \
            }                                                                 \
        _Pragma("unroll")                                                     \
        for (int t2 = 0; t2 < 2; t2++)                                        \
            if (a_u_r < 64)                                                   \
                cp16((stage_base) + 2 * TILE_A + t2 * TILE_W                  \
                         + a_u_r * AST_B + u_c16,                             \
                     Ws[t2] + a_u_r * 64 + u_c16);                            \
    } while (0)

    GEMM_LOADS(sb0, 0);
    CP_COMMIT();

    for (int kc = 0; kc < NC_; kc++) {
        if (kc + 1 < NC_) {
            uint32_t sb = sb0 + ((kc + 1) & 1) * STAGE_SM;
            GEMM_LOADS(sb, kc + 1);
            CP_COMMIT();
            CP_WAIT(1);
        } else {
            CP_WAIT(0);
        }
        __syncthreads();

        const uint32_t st = sb0 + (kc & 1) * STAGE_SM;
        const uint32_t Ahi_b = st, Alo_b = st + TILE_A;
        const uint32_t Whi_b = st + 2 * TILE_A, Wlo_b = st + 2 * TILE_A + TILE_W;
#pragma unroll
        for (int k16 = 0; k16 < 2; k16++) {
            uint32_t bh[8], bl[8];
            ldmx4(bh,     Whi_b + (w_r)      * AST_B + k16 * 32 + w_kb);
            ldmx4(bh + 4, Whi_b + (w_r + 16) * AST_B + k16 * 32 + w_kb);
            ldmx4(bl,     Wlo_b + (w_r)      * AST_B + k16 * 32 + w_kb);
            ldmx4(bl + 4, Wlo_b + (w_r + 16) * AST_B + k16 * 32 + w_kb);
#pragma unroll
            for (int mi = 0; mi < 2; mi++) {
                uint32_t a[4];
                ldmx4(a, Ahi_b + (a_r + mi * 16) * AST_B + k16 * 32 + a_kb);
#pragma unroll
                for (int ni = 0; ni < 4; ni++) mma_bf16(acc[mi][ni], a, bh + ni * 2);
#pragma unroll
                for (int ni = 0; ni < 4; ni++) mma_bf16(acc[mi][ni], a, bl + ni * 2);
            }
#pragma unroll
            for (int mi = 0; mi < 2; mi++) {
                uint32_t a[4];
                ldmx4(a, Alo_b + (a_r + mi * 16) * AST_B + k16 * 32 + a_kb);
#pragma unroll
                for (int ni = 0; ni < 4; ni++) mma_bf16(acc[mi][ni], a, bh + ni * 2);
            }
        }
        __syncthreads();
    }

    // ---- epilogue ----
    const int r0 = rt * 128 + wm * 32 + (lane >> 2);
    const int c0 = nh * 64 + wn * 32 + (lane & 3) * 2;
    if (tb < T_) {
        const float* bias = Wk_b + tb * C_;
        __nv_bfloat16* ph = g_Phi + (size_t)tb * B_ * C_;
        __nv_bfloat16* pl = g_Plo + (size_t)tb * B_ * C_;
#pragma unroll
        for (int mi = 0; mi < 2; mi++)
#pragma unroll
            for (int ni = 0; ni < 4; ni++) {
                int row = r0 + mi * 16, col = c0 + ni * 8;
                float b0 = __ldg(bias + col), b1 = __ldg(bias + col + 1);
#pragma unroll
                for (int h = 0; h < 2; h++) {
                    float v0 = acc[mi][ni][h * 2]     + b0;
                    float v1 = acc[mi][ni][h * 2 + 1] + b1;
                    __nv_bfloat162 hh, ll;
                    hh.x = __float2bfloat16(v0);
                    ll.x = __float2bfloat16(v0 - __bfloat162float(hh.x));
                    hh.y = __float2bfloat16(v1);
                    ll.y = __float2bfloat16(v1 - __bfloat162float(hh.y));
                    size_t off = (size_t)(row + h * 8) * C_ + col;
                    *(__nv_bfloat162*)(ph + off) = hh;
                    *(__nv_bfloat162*)(pl + off) = ll;
                }
            }
    } else {
        const float* bias = pb1;
#pragma unroll
        for (int mi = 0; mi < 2; mi++)
#pragma unroll
            for (int ni = 0; ni < 4; ni++) {
                int row = r0 + mi * 16, col = c0 + ni * 8;
                float b0 = __ldg(bias + col), b1 = __ldg(bias + col + 1);
                float2 v;
                v.x = acc[mi][ni][0] + b0; v.y = acc[mi][ni][1] + b1;
                *(float2*)(g_h + (size_t)row * C_ + col) = v;
                v.x = acc[mi][ni][2] + b0; v.y = acc[mi][ni][3] + b1;
                *(float2*)(g_h + (size_t)(row + 8) * C_ + col) = v;
            }
    }
#undef GEMM_LOADS
}

// ---------------- flash NCE via mma.sync: block = 128 q-rows x t -----------
#define FST 272                     // 128 bf16 + 16B pad
#define FTILE_ (128 * FST)          // 34816
#define FL_REDM (6 * FTILE_)
#define FL_REDL (FL_REDM + 1024)
#define FL_DIAG (FL_REDL + 1024)
#define FL_SMEM (FL_DIAG + 512)     // 211456 bytes

__global__ __launch_bounds__(256, 1) void flash_mma_kernel()
{
    extern __shared__ __align__(128) char smem[];
    const uint32_t sb = smem_u32(smem);
    float* red_m = (float*)(smem + FL_REDM);
    float* red_l = (float*)(smem + FL_REDL);
    float* diag  = (float*)(smem + FL_DIAG);

    const int rb = blockIdx.x, t = blockIdx.y;
    const int tid = threadIdx.x, lane = tid & 31, wid = tid >> 5;
    const int wm = wid >> 1, wn = wid & 1;      // warp tile 32 x 64

    const __nv_bfloat16* Ehi = g_Ehi + ((size_t)t * B_ + rb * 128) * C_;
    const __nv_bfloat16* Elo = g_Elo + ((size_t)t * B_ + rb * 128) * C_;
    const __nv_bfloat16* Phi = g_Phi + (size_t)t * B_ * C_;
    const __nv_bfloat16* Plo = g_Plo + (size_t)t * B_ * C_;

#pragma unroll
    for (int f = 0; f < 8; f++) {
        int id = tid + f * 256, r = id >> 4, ch = (id & 15) << 4;
        cp16(sb + r * FST + ch,          (const char*)Ehi + r * 256 + ch);
        cp16(sb + FTILE_ + r * FST + ch, (const char*)Elo + r * 256 + ch);
    }
    CP_COMMIT();
#pragma unroll
    for (int f = 0; f < 8; f++) {
        int id = tid + f * 256, r = id >> 4, ch = (id & 15) << 4;
        cp16(sb + 2 * FTILE_ + r * FST + ch, (const char*)Phi + r * 256 + ch);
        cp16(sb + 3 * FTILE_ + r * FST + ch, (const char*)Plo + r * 256 + ch);
    }
    CP_COMMIT();

    float m_r[4], l_r[4];
#pragma unroll
    for (int r = 0; r < 4; r++) { m_r[r] = -3.0e38f; l_r[r] = 0.0f; }

    const int a_rr = wm * 32 + (lane & 15);
    const int a_kb = (lane >> 4) << 4;
    const int b_rr = wn * 64 + (lane & 7) + ((lane >> 4) << 3);
    const int b_kb = ((lane >> 3) & 1) << 4;
    const int row4 = lane >> 2;

    for (int kt = 0; kt < 16; kt++) {
        if (kt + 1 < 16) {
            uint32_t kb = sb + (2 + ((kt + 1) & 1) * 2) * FTILE_;
            const char* sh = (const char*)Phi + (size_t)(kt + 1) * 128 * 256;
            const char* sl = (const char*)Plo + (size_t)(kt + 1) * 128 * 256;
#pragma unroll
            for (int f = 0; f < 8; f++) {
                int id = tid + f * 256, r = id >> 4, ch = (id & 15) << 4;
                cp16(kb + r * FST + ch,          sh + r * 256 + ch);
                cp16(kb + FTILE_ + r * FST + ch, sl + r * 256 + ch);
            }
            CP_COMMIT();
            CP_WAIT(1);
        } else {
            CP_WAIT(0);
        }
        __syncthreads();

        const uint32_t Qh = sb, Ql = sb + FTILE_;
        const uint32_t Kh = sb + (2 + (kt & 1) * 2) * FTILE_;
        const uint32_t Kl = Kh + FTILE_;

        float acc[2][8][4];
#pragma unroll
        for (int mi = 0; mi < 2; mi++)
#pragma unroll
            for (int ni = 0; ni < 8; ni++)
#pragma unroll
                for (int q = 0; q < 4; q++) acc[mi][ni][q] = 0.0f;

#pragma unroll
        for (int k16 = 0; k16 < 8; k16++) {
            uint32_t bh[16], bl[16];
#pragma unroll
            for (int g = 0; g < 4; g++) {
                ldmx4(bh + g * 4, Kh + (b_rr + g * 16) * FST + k16 * 32 + b_kb);
                ldmx4(bl + g * 4, Kl + (b_rr + g * 16) * FST + k16 * 32 + b_kb);
            }
#pragma unroll
            for (int mi = 0; mi < 2; mi++) {
                uint32_t a[4];
                ldmx4(a, Qh + (a_rr + mi * 16) * FST + k16 * 32 + a_kb);
#pragma unroll
                for (int ni = 0; ni < 8; ni++) mma_bf16(acc[mi][ni], a, bh + ni * 2);
#pragma unroll
                for (int ni = 0; ni < 8; ni++) mma_bf16(acc[mi][ni], a, bl + ni * 2);
            }
#pragma unroll
            for (int mi = 0; mi < 2; mi++) {
                uint32_t a[4];
                ldmx4(a, Ql + (a_rr + mi * 16) * FST + k16 * 32 + a_kb);
#pragma unroll
                for (int ni = 0; ni < 8; ni++) mma_bf16(acc[mi][ni], a, bh + ni * 2);
            }
        }

        float rmax[4];
#pragma unroll
        for (int mi = 0; mi < 2; mi++)
#pragma unroll
            for (int h = 0; h < 2; h++) {
                float m = acc[mi][0][h * 2];
#pragma unroll
                for (int ni = 0; ni < 8; ni++) {
                    m = fmaxf(m, acc[mi][ni][h * 2]);
                    m = fmaxf(m, acc[mi][ni][h * 2 + 1]);
                }
                rmax[mi * 2 + h] = m;
            }
#pragma unroll
        for (int r = 0; r < 4; r++) {
            rmax[r] = fmaxf(rmax[r], __shfl_xor_sync(0xffffffffu, rmax[r], 1));
            rmax[r] = fmaxf(rmax[r], __shfl_xor_sync(0xffffffffu, rmax[r], 2));
        }
        if ((lane & 3) == 0) {
#pragma unroll
            for (int r = 0; r < 4; r++) {
                int rg = wm * 32 + (r >> 1) * 16 + row4 + (r & 1) * 8;
                red_m[rg * 2 + wn] = rmax[r];
            }
        }
        __syncthreads();

        float m_new[4], s_r[4];
#pragma unroll
        for (int r = 0; r < 4; r++) {
            int rg = wm * 32 + (r >> 1) * 16 + row4 + (r & 1) * 8;
            float tm = fmaxf(red_m[rg * 2], red_m[rg * 2 + 1]);
            m_new[r] = fmaxf(m_r[r], tm);
        }
#pragma unroll
        for (int mi = 0; mi < 2; mi++)
#pragma unroll
            for (int h = 0; h < 2; h++) {
                float mn = m_new[mi * 2 + h];
                float s = 0.0f;
#pragma unroll
                for (int ni = 0; ni < 8; ni++) {
                    s += __expf(acc[mi][ni][h * 2] - mn);
                    s += __expf(acc[mi][ni][h * 2 + 1] - mn);
                }
                s_r[mi * 2 + h] = s;
            }
#pragma unroll
        for (int r = 0; r < 4; r++) {
            s_r[r] += __shfl_xor_sync(0xffffffffu, s_r[r], 1);
            s_r[r] += __shfl_xor_sync(0xffffffffu, s_r[r], 2);
        }
        if ((lane & 3) == 0) {
#pragma unroll
            for (int r = 0; r < 4; r++) {
                int rg = wm * 32 + (r >> 1) * 16 + row4 + (r & 1) * 8;
                red_l[rg * 2 + wn] = s_r[r];
            }
        }
        if (kt == rb) {
#pragma unroll
            for (int mi = 0; mi < 2; mi++)
#pragma unroll
                for (int ni = 0; ni < 8; ni++)
#pragma unroll
                    for (int q = 0; q < 4; q++) {
                        int rl = wm * 32 + mi * 16 + row4 + (q >> 1) * 8;
                        int cl = wn * 64 + ni * 8 + (lane & 3) * 2 + (q & 1);
                        if (rl == cl) diag[rl] = acc[mi][ni][q];
                    }
        }
        __syncthreads();
#pragma unroll
        for (int r = 0; r < 4; r++) {
            int rg = wm * 32 + (r >> 1) * 16 + row4 + (r & 1) * 8;
            float ts = red_l[rg * 2] + red_l[rg * 2 + 1];
            l_r[r] = l_r[r] * __expf(m_r[r] - m_new[r]) + ts;
            m_r[r] = m_new[r];
        }
    }

    if (wn == 0 && (lane & 3) == 0) {
        float v = 0.0f;
#pragma unroll
        for (int r = 0; r < 4; r++) {
            int rg = wm * 32 + (r >> 1) * 16 + row4 + (r & 1) * 8;
            v += diag[rg] - (m_r[r] + logf(l_r[r]));
        }
        atomicAdd(&g_nce, v);
    }
}

// ---------------- BatchNorm statistics -------------------------------------
__global__ void bnstat_kernel()
{
    const int c   = blockIdx.x;
    const int tid = threadIdx.x;
    float s = 0.0f, sq = 0.0f;
    for (int b = tid; b < B_; b += 256) {
        float v = g_h[(size_t)b * C_ + c];
        s += v;
        sq = fmaf(v, v, sq);
    }
    __shared__ float ss[256], sqq[256];
    ss[tid] = s; sqq[tid] = sq;
    __syncthreads();
    for (int st = 128; st > 0; st >>= 1) {
        if (tid < st) { ss[tid] += ss[tid + st]; sqq[tid] += sqq[tid + st]; }
        __syncthreads();
    }
    if (tid == 0) {
        float mean = ss[0] * (1.0f / B_);
        float var  = sqq[0] * (1.0f / B_) - mean * mean;
        g_mean[c] = mean;
        g_rstd[c] = rsqrtf(var + 1e-5f);
    }
}

// ---------------- projection head ------------------------------------------
__global__ void proj_kernel(const float* __restrict__ gamma,
                            const float* __restrict__ beta,
                            const float* __restrict__ pw2,
                            const float* __restrict__ pb2,
                            float* __restrict__ out)
{
    __shared__ float w2s[P_][132];
    __shared__ float hn[32][129];
    __shared__ float mg[C_], bg[C_];

    const int tid  = threadIdx.x;
    const int base = blockIdx.x * 32;

    for (int f = tid; f < P_ * C_; f += 256) {
        int p = f >> 7, c = f & 127;
        w2s[p][c] = pw2[f];
    }
    if (tid < C_) {
        float sc = g_rstd[tid] * gamma[tid];
        mg[tid] = sc;
        bg[tid] = beta[tid] - g_mean[tid] * sc;
    }
    __syncthreads();

    for (int f = tid; f < 32 * C_; f += 256) {
        int r = f >> 7, c = f & 127;
        float v = g_h[(size_t)(base + r) * C_ + c];
        v = v * mg[c] + bg[c];
        v = (v >= 0.0f) ? v : 0.01f * v;
        hn[r][c] = v;
    }
    __syncthreads();

    const int r  = tid >> 3;
    const int pg = (tid & 7) * 4;
    float accp[4];
#pragma unroll
    for (int p = 0; p < 4; p++) accp[p] = 0.0f;
    for (int c = 0; c < C_; c++) {
        float hv = hn[r][c];
#pragma unroll
        for (int p = 0; p < 4; p++)
            accp[p] = fmaf(hv, w2s[pg + p][c], accp[p]);
    }
#pragma unroll
    for (int p = 0; p < 4; p++)
        out[1 + (size_t)(base + r) * P_ + pg + p] = accp[p] + pb2[pg + p];

    if (blockIdx.x == 0 && tid == 0)
        out[0] = g_nce * (-1.0f / (float)(B_ * T_));
}

// ---------------- launch ---------------------------------------------------
extern "C" void kernel_launch(void* const* d_in, const int* in_sizes, int n_in,
                              void* d_out, int out_size)
{
    const float* z     = (const float*)d_in[0];
    const float* c_t   = (const float*)d_in[1];
    const float* Wk_w  = (const float*)d_in[2];
    const float* Wk_b  = (const float*)d_in[3];
    const float* pw1   = (const float*)d_in[4];
    const float* pb1   = (const float*)d_in[5];
    const float* gamma = (const float*)d_in[6];
    const float* beta  = (const float*)d_in[7];
    const float* pw2   = (const float*)d_in[8];
    const float* pb2   = (const float*)d_in[9];
    float* out = (float*)d_out;

    init_kernel<<<(B_ * C_ + 255) / 256, 256>>>(z);
    convA_kernel<<<(B_ * D_ / 4) / 256, 256>>>(c_t);
    convW_kernel<<<(NT * C_ * D_ / 4) / 256, 256>>>(Wk_w, pw1);

    cudaFuncSetAttribute(gemm_mma_kernel,
                         cudaFuncAttributeMaxDynamicSharedMemorySize, GEMM_SMEM);
    gemm_mma_kernel<<<dim3(NT, 32), 256, GEMM_SMEM>>>(Wk_b, pb1);

    cudaFuncSetAttribute(flash_mma_kernel,
                         cudaFuncAttributeMaxDynamicSharedMemorySize, FL_SMEM);
    flash_mma_kernel<<<dim3(B_ / 128, T_), 256, FL_SMEM>>>();

    bnstat_kernel<<<C_, 256>>>();
    proj_kernel<<<B_ / 32, 256>>>(gamma, beta, pw2, pb2, out);
}

// round 8
// speedup vs baseline: 3.1686x; 1.0751x over previous
#include <cuda_runtime.h>
#include <cuda_bf16.h>
#include <cstdint>

#define B_ 2048
#define T_ 18
#define C_ 128
#define D_ 4096
#define P_ 32
#define NT 19               // 18 timesteps + pw1 block
#define NC_ (D_ / 32)       // 128 K-chunks of 32 bf16
#define NCH 64              // K-chunks per half (K-split x2)
#define AST_B 80            // gemm smem row stride (32 bf16 + 16B pad)
#define TILE_A (128 * AST_B)        // 10240
#define TILE_W (64 * AST_B)         // 5120
#define STAGE_SM (2 * TILE_A + 2 * TILE_W)   // 30720
#define GEMM_SMEM (2 * STAGE_SM)             // 61440

// ---------------- scratch (device globals; no allocation allowed) ----------
__device__ float g_h   [B_ * C_];
__device__ float g_mean[C_];
__device__ float g_rstd[C_];
__device__ float g_nce;

// fp32 partial accumulators for the K-split GEMM: [t][b][c]
__device__ __align__(16) float g_acc0[NT * B_ * C_];
__device__ __align__(16) float g_acc1[NT * B_ * C_];

// bf16 hi/lo GEMM operand tiles: [rowtile/t][kchunk][128 rows][32 cols]
__device__ __align__(16) __nv_bfloat16 g_Ahi[16 * NC_ * 4096];
__device__ __align__(16) __nv_bfloat16 g_Alo[16 * NC_ * 4096];
__device__ __align__(16) __nv_bfloat16 g_Whi[NT * NC_ * 4096];
__device__ __align__(16) __nv_bfloat16 g_Wlo[NT * NC_ * 4096];

// bf16 hi/lo enc + pred for flash: [t][b][c] row-major (C=128)
__device__ __align__(16) __nv_bfloat16 g_Ehi[T_ * B_ * C_];
__device__ __align__(16) __nv_bfloat16 g_Elo[T_ * B_ * C_];
__device__ __align__(16) __nv_bfloat16 g_Phi[T_ * B_ * C_];
__device__ __align__(16) __nv_bfloat16 g_Plo[T_ * B_ * C_];

// ---------------- helpers ---------------------------------------------------
__device__ __forceinline__ uint32_t smem_u32(const void* p) {
    uint32_t a;
    asm("{ .reg .u64 t; cvta.to.shared.u64 t, %1; cvt.u32.u64 %0, t; }"
        : "=r"(a) : "l"(p));
    return a;
}

__device__ __forceinline__ void cp16(uint32_t dst, const void* src) {
    asm volatile("cp.async.cg.shared.global [%0], [%1], 16;"
                 :: "r"(dst), "l"(src) : "memory");
}
#define CP_COMMIT() asm volatile("cp.async.commit_group;" ::: "memory")
#define CP_WAIT(N)  asm volatile("cp.async.wait_group %0;" :: "n"(N) : "memory")

__device__ __forceinline__ void ldmx4(uint32_t* r, uint32_t addr) {
    asm volatile("ldmatrix.sync.aligned.m8n8.x4.shared.b16 {%0,%1,%2,%3}, [%4];"
                 : "=r"(r[0]), "=r"(r[1]), "=r"(r[2]), "=r"(r[3]) : "r"(addr));
}

__device__ __forceinline__ void mma_bf16(float* c, const uint32_t* a,
                                         const uint32_t* b) {
    asm volatile(
        "mma.sync.aligned.m16n8k16.row.col.f32.bf16.bf16.f32 "
        "{%0,%1,%2,%3}, {%4,%5,%6,%7}, {%8,%9}, {%0,%1,%2,%3};"
        : "+f"(c[0]), "+f"(c[1]), "+f"(c[2]), "+f"(c[3])
        : "r"(a[0]), "r"(a[1]), "r"(a[2]), "r"(a[3]), "r"(b[0]), "r"(b[1]));
}

// ---------------- init: z_aug2 [B,C,T] -> Ehi/Elo [T,B,C]; zero nce --------
__global__ void init_kernel(const float* __restrict__ z)
{
    int bc = blockIdx.x * blockDim.x + threadIdx.x;
    if (bc == 0) g_nce = 0.0f;
    if (bc < B_ * C_) {
        const float* src = z + (size_t)bc * T_;
#pragma unroll
        for (int t = 0; t < T_; t++) {
            float v = src[t];
            __nv_bfloat16 hi = __float2bfloat16(v);
            __nv_bfloat16 lo = __float2bfloat16(v - __bfloat162float(hi));
            g_Ehi[(size_t)t * B_ * C_ + bc] = hi;
            g_Elo[(size_t)t * B_ * C_ + bc] = lo;
        }
    }
}

// ---------------- pack A (c_t) into bf16 hi/lo GEMM tiles -------------------
__global__ void convA_kernel(const float* __restrict__ A)
{
    int i  = blockIdx.x * 256 + threadIdx.x;
    int gr = i >> 10;
    int k4 = (i & 1023) << 2;
    float4 v = *(const float4*)(A + (size_t)gr * D_ + k4);
    float f[4] = {v.x, v.y, v.z, v.w};
    __nv_bfloat162 h0, h1, l0, l1;
    {
        __nv_bfloat16 hi[4], lo[4];
#pragma unroll
        for (int j = 0; j < 4; j++) {
            hi[j] = __float2bfloat16(f[j]);
            lo[j] = __float2bfloat16(f[j] - __bfloat162float(hi[j]));
        }
        h0.x = hi[0]; h0.y = hi[1]; h1.x = hi[2]; h1.y = hi[3];
        l0.x = lo[0]; l0.y = lo[1]; l1.x = lo[2]; l1.y = lo[3];
    }
    int rt = gr >> 7, row = gr & 127, kc = k4 >> 5, col = k4 & 31;
    size_t off = (((size_t)(rt * NC_ + kc) * 128) + row) * 32 + col;
    *(__nv_bfloat162*)(g_Ahi + off)     = h0;
    *(__nv_bfloat162*)(g_Ahi + off + 2) = h1;
    *(__nv_bfloat162*)(g_Alo + off)     = l0;
    *(__nv_bfloat162*)(g_Alo + off + 2) = l1;
}

// ---------------- pack W (Wk_w + pw1) into bf16 hi/lo GEMM tiles ------------
__global__ void convW_kernel(const float* __restrict__ Wk_w,
                             const float* __restrict__ pw1)
{
    int i  = blockIdx.x * 256 + threadIdx.x;
    int rw = i >> 10;
    int k4 = (i & 1023) << 2;
    int t = rw >> 7, n = rw & 127;
    const float* src = (t < T_) ? (Wk_w + ((size_t)t * C_ + n) * D_ + k4)
                                : (pw1 + (size_t)n * D_ + k4);
    float4 v = *(const float4*)src;
    float f[4] = {v.x, v.y, v.z, v.w};
    __nv_bfloat162 h0, h1, l0, l1;
    {
        __nv_bfloat16 hi[4], lo[4];
#pragma unroll
        for (int j = 0; j < 4; j++) {
            hi[j] = __float2bfloat16(f[j]);
            lo[j] = __float2bfloat16(f[j] - __bfloat162float(hi[j]));
        }
        h0.x = hi[0]; h0.y = hi[1]; h1.x = hi[2]; h1.y = hi[3];
        l0.x = lo[0]; l0.y = lo[1]; l1.x = lo[2]; l1.y = lo[3];
    }
    int kc = k4 >> 5, col = k4 & 31;
    size_t off = (((size_t)(t * NC_ + kc) * 128) + n) * 32 + col;
    *(__nv_bfloat162*)(g_Whi + off)     = h0;
    *(__nv_bfloat162*)(g_Whi + off + 2) = h1;
    *(__nv_bfloat162*)(g_Wlo + off)     = l0;
    *(__nv_bfloat162*)(g_Wlo + off + 2) = l1;
}

// ---------------- mma.sync GEMM (K-split x2): C[128x64] per unit -----------
// grid (NT, 64): by bits -> kh = by&1, nh = (by>>1)&1, rt = by>>2
// Each unit computes K range [kh*2048, +2048) and stores fp32 partials to
// g_acc0 (kh=0) or g_acc1 (kh=1). No bias here.
__global__ __launch_bounds__(256, 3) void gemm_mma_kernel()
{
    extern __shared__ __align__(128) char smem[];
    const uint32_t sb0 = smem_u32(smem);

    const int tid  = threadIdx.x;
    const int lane = tid & 31, wid = tid >> 5;
    const int wm = wid >> 1, wn = wid & 1;
    const int tb = blockIdx.x;
    const int kh = blockIdx.y & 1;
    const int nh = (blockIdx.y >> 1) & 1;
    const int rt = blockIdx.y >> 2;
    const int kc0 = kh * NCH;

    float acc[2][4][4];
#pragma unroll
    for (int mi = 0; mi < 2; mi++)
#pragma unroll
        for (int ni = 0; ni < 4; ni++)
#pragma unroll
            for (int q = 0; q < 4; q++) acc[mi][ni][q] = 0.0f;

    const int a_r  = wm * 32 + (lane & 15);
    const int a_kb = (lane >> 4) << 4;
    const int w_r  = wn * 32 + (lane & 7) + ((lane >> 4) << 3);
    const int w_kb = ((lane >> 3) & 1) << 4;

    const int a_u_r  = tid >> 2;
    const int u_c16  = (tid & 3) << 4;

#define GEMM_LOADS(stage_base, kcL)                                           \
    do {                                                                      \
        const char* As[2] = {                                                 \
            (const char*)(g_Ahi + (((size_t)(rt * NC_ + (kcL))) << 12)),      \
            (const char*)(g_Alo + (((size_t)(rt * NC_ + (kcL))) << 12))};     \
        const char* Ws[2] = {                                                 \
            (const char*)(g_Whi + (((size_t)(tb * NC_ + (kcL))) << 12))       \
                + nh * 4096,                                                  \
            (const char*)(g_Wlo + (((size_t)(tb * NC_ + (kcL))) << 12))       \
                + nh * 4096};                                                 \
        _Pragma("unroll")                                                     \
        for (int t2 = 0; t2 < 2; t2++)                                        \
            _Pragma("unroll")                                                 \
            for (int j = 0; j < 2; j++) {                                     \
                int row = a_u_r + j * 64;                                     \
                cp16((stage_base) + t2 * TILE_A + row * AST_B + u_c16,        \
                     As[t2] + row * 64 + u_c16);                              \
            }                                                                 \
        _Pragma("unroll")                                                     \
        for (int t2 = 0; t2 < 2; t2++)                                        \
            if (a_u_r < 64)                                                   \
                cp16((stage_base) + 2 * TILE_A + t2 * TILE_W                  \
                         + a_u_r * AST_B + u_c16,                             \
                     Ws[t2] + a_u_r * 64 + u_c16);                            \
    } while (0)

    GEMM_LOADS(sb0, kc0);
    CP_COMMIT();

    for (int kc = 0; kc < NCH; kc++) {
        if (kc + 1 < NCH) {
            uint32_t sb = sb0 + ((kc + 1) & 1) * STAGE_SM;
            GEMM_LOADS(sb, kc0 + kc + 1);
            CP_COMMIT();
            CP_WAIT(1);
        } else {
            CP_WAIT(0);
        }
        __syncthreads();

        const uint32_t st = sb0 + (kc & 1) * STAGE_SM;
        const uint32_t Ahi_b = st, Alo_b = st + TILE_A;
        const uint32_t Whi_b = st + 2 * TILE_A, Wlo_b = st + 2 * TILE_A + TILE_W;
#pragma unroll
        for (int k16 = 0; k16 < 2; k16++) {
            uint32_t bh[8], bl[8];
            ldmx4(bh,     Whi_b + (w_r)      * AST_B + k16 * 32 + w_kb);
            ldmx4(bh + 4, Whi_b + (w_r + 16) * AST_B + k16 * 32 + w_kb);
            ldmx4(bl,     Wlo_b + (w_r)      * AST_B + k16 * 32 + w_kb);
            ldmx4(bl + 4, Wlo_b + (w_r + 16) * AST_B + k16 * 32 + w_kb);
#pragma unroll
            for (int mi = 0; mi < 2; mi++) {
                uint32_t a[4];
                ldmx4(a, Ahi_b + (a_r + mi * 16) * AST_B + k16 * 32 + a_kb);
#pragma unroll
                for (int ni = 0; ni < 4; ni++) mma_bf16(acc[mi][ni], a, bh + ni * 2);
#pragma unroll
                for (int ni = 0; ni < 4; ni++) mma_bf16(acc[mi][ni], a, bl + ni * 2);
            }
#pragma unroll
            for (int mi = 0; mi < 2; mi++) {
                uint32_t a[4];
                ldmx4(a, Alo_b + (a_r + mi * 16) * AST_B + k16 * 32 + a_kb);
#pragma unroll
                for (int ni = 0; ni < 4; ni++) mma_bf16(acc[mi][ni], a, bh + ni * 2);
            }
        }
        __syncthreads();
    }

    // ---- epilogue: fp32 partial store (disjoint per kh) ----
    float* outp = (kh ? g_acc1 : g_acc0) + (size_t)tb * B_ * C_;
    const int r0 = rt * 128 + wm * 32 + (lane >> 2);
    const int c0 = nh * 64 + wn * 32 + (lane & 3) * 2;
#pragma unroll
    for (int mi = 0; mi < 2; mi++)
#pragma unroll
        for (int ni = 0; ni < 4; ni++) {
            int row = r0 + mi * 16, col = c0 + ni * 8;
            float2 v;
            v.x = acc[mi][ni][0]; v.y = acc[mi][ni][1];
            *(float2*)(outp + (size_t)row * C_ + col) = v;
            v.x = acc[mi][ni][2]; v.y = acc[mi][ni][3];
            *(float2*)(outp + (size_t)(row + 8) * C_ + col) = v;
        }
#undef GEMM_LOADS
}

// ---------------- combine: acc0+acc1+bias -> Phi/Plo (t<18) or g_h ---------
__global__ void combine_kernel(const float* __restrict__ Wk_b,
                               const float* __restrict__ pb1)
{
    const int per_t = B_ * C_ / 4;                 // float4s per timestep
    int i = blockIdx.x * 256 + threadIdx.x;        // 0 .. NT*per_t-1
    int t = i / per_t;
    int r = i - t * per_t;                         // float4 index within [B,C]
    int c = (r & 31) << 2;                         // column 0..124

    const float4 v0 = *((const float4*)g_acc0 + i);
    const float4 v1 = *((const float4*)g_acc1 + i);
    const float* bias = (t < T_) ? (Wk_b + t * C_) : pb1;
    float s[4];
    s[0] = v0.x + v1.x + __ldg(bias + c + 0);
    s[1] = v0.y + v1.y + __ldg(bias + c + 1);
    s[2] = v0.z + v1.z + __ldg(bias + c + 2);
    s[3] = v0.w + v1.w + __ldg(bias + c + 3);

    if (t < T_) {
        __nv_bfloat162 h0, h1, l0, l1;
        h0.x = __float2bfloat16(s[0]);
        l0.x = __float2bfloat16(s[0] - __bfloat162float(h0.x));
        h0.y = __float2bfloat16(s[1]);
        l0.y = __float2bfloat16(s[1] - __bfloat162float(h0.y));
        h1.x = __float2bfloat16(s[2]);
        l1.x = __float2bfloat16(s[2] - __bfloat162float(h1.x));
        h1.y = __float2bfloat16(s[3]);
        l1.y = __float2bfloat16(s[3] - __bfloat162float(h1.y));
        size_t off = (size_t)t * B_ * C_ + (size_t)r * 4;
        *(__nv_bfloat162*)(g_Phi + off)     = h0;
        *(__nv_bfloat162*)(g_Phi + off + 2) = h1;
        *(__nv_bfloat162*)(g_Plo + off)     = l0;
        *(__nv_bfloat162*)(g_Plo + off + 2) = l1;
    } else {
        float4 o; o.x = s[0]; o.y = s[1]; o.z = s[2]; o.w = s[3];
        *((float4*)g_h + r) = o;
    }
}

// ---------------- flash NCE via mma.sync: block = 128 q-rows x t -----------
#define FST 272                     // 128 bf16 + 16B pad
#define FTILE_ (128 * FST)          // 34816
#define FL_REDM (6 * FTILE_)
#define FL_REDL (FL_REDM + 1024)
#define FL_DIAG (FL_REDL + 1024)
#define FL_SMEM (FL_DIAG + 512)     // 211456 bytes

__global__ __launch_bounds__(256, 1) void flash_mma_kernel()
{
    extern __shared__ __align__(128) char smem[];
    const uint32_t sb = smem_u32(smem);
    float* red_m = (float*)(smem + FL_REDM);
    float* red_l = (float*)(smem + FL_REDL);
    float* diag  = (float*)(smem + FL_DIAG);

    const int rb = blockIdx.x, t = blockIdx.y;
    const int tid = threadIdx.x, lane = tid & 31, wid = tid >> 5;
    const int wm = wid >> 1, wn = wid & 1;      // warp tile 32 x 64

    const __nv_bfloat16* Ehi = g_Ehi + ((size_t)t * B_ + rb * 128) * C_;
    const __nv_bfloat16* Elo = g_Elo + ((size_t)t * B_ + rb * 128) * C_;
    const __nv_bfloat16* Phi = g_Phi + (size_t)t * B_ * C_;
    const __nv_bfloat16* Plo = g_Plo + (size_t)t * B_ * C_;

#pragma unroll
    for (int f = 0; f < 8; f++) {
        int id = tid + f * 256, r = id >> 4, ch = (id & 15) << 4;
        cp16(sb + r * FST + ch,          (const char*)Ehi + r * 256 + ch);
        cp16(sb + FTILE_ + r * FST + ch, (const char*)Elo + r * 256 + ch);
    }
    CP_COMMIT();
#pragma unroll
    for (int f = 0; f < 8; f++) {
        int id = tid + f * 256, r = id >> 4, ch = (id & 15) << 4;
        cp16(sb + 2 * FTILE_ + r * FST + ch, (const char*)Phi + r * 256 + ch);
        cp16(sb + 3 * FTILE_ + r * FST + ch, (const char*)Plo + r * 256 + ch);
    }
    CP_COMMIT();

    float m_r[4], l_r[4];
#pragma unroll
    for (int r = 0; r < 4; r++) { m_r[r] = -3.0e38f; l_r[r] = 0.0f; }

    const int a_rr = wm * 32 + (lane & 15);
    const int a_kb = (lane >> 4) << 4;
    const int b_rr = wn * 64 + (lane & 7) + ((lane >> 4) << 3);
    const int b_kb = ((lane >> 3) & 1) << 4;
    const int row4 = lane >> 2;

    for (int kt = 0; kt < 16; kt++) {
        if (kt + 1 < 16) {
            uint32_t kb = sb + (2 + ((kt + 1) & 1) * 2) * FTILE_;
            const char* sh = (const char*)Phi + (size_t)(kt + 1) * 128 * 256;
            const char* sl = (const char*)Plo + (size_t)(kt + 1) * 128 * 256;
#pragma unroll
            for (int f = 0; f < 8; f++) {
                int id = tid + f * 256, r = id >> 4, ch = (id & 15) << 4;
                cp16(kb + r * FST + ch,          sh + r * 256 + ch);
                cp16(kb + FTILE_ + r * FST + ch, sl + r * 256 + ch);
            }
            CP_COMMIT();
            CP_WAIT(1);
        } else {
            CP_WAIT(0);
        }
        __syncthreads();

        const uint32_t Qh = sb, Ql = sb + FTILE_;
        const uint32_t Kh = sb + (2 + (kt & 1) * 2) * FTILE_;
        const uint32_t Kl = Kh + FTILE_;

        float acc[2][8][4];
#pragma unroll
        for (int mi = 0; mi < 2; mi++)
#pragma unroll
            for (int ni = 0; ni < 8; ni++)
#pragma unroll
                for (int q = 0; q < 4; q++) acc[mi][ni][q] = 0.0f;

#pragma unroll
        for (int k16 = 0; k16 < 8; k16++) {
            uint32_t bh[16], bl[16];
#pragma unroll
            for (int g = 0; g < 4; g++) {
                ldmx4(bh + g * 4, Kh + (b_rr + g * 16) * FST + k16 * 32 + b_kb);
                ldmx4(bl + g * 4, Kl + (b_rr + g * 16) * FST + k16 * 32 + b_kb);
            }
#pragma unroll
            for (int mi = 0; mi < 2; mi++) {
                uint32_t a[4];
                ldmx4(a, Qh + (a_rr + mi * 16) * FST + k16 * 32 + a_kb);
#pragma unroll
                for (int ni = 0; ni < 8; ni++) mma_bf16(acc[mi][ni], a, bh + ni * 2);
#pragma unroll
                for (int ni = 0; ni < 8; ni++) mma_bf16(acc[mi][ni], a, bl + ni * 2);
            }
#pragma unroll
            for (int mi = 0; mi < 2; mi++) {
                uint32_t a[4];
                ldmx4(a, Ql + (a_rr + mi * 16) * FST + k16 * 32 + a_kb);
#pragma unroll
                for (int ni = 0; ni < 8; ni++) mma_bf16(acc[mi][ni], a, bh + ni * 2);
            }
        }

        float rmax[4];
#pragma unroll
        for (int mi = 0; mi < 2; mi++)
#pragma unroll
            for (int h = 0; h < 2; h++) {
                float m = acc[mi][0][h * 2];
#pragma unroll
                for (int ni = 0; ni < 8; ni++) {
                    m = fmaxf(m, acc[mi][ni][h * 2]);
                    m = fmaxf(m, acc[mi][ni][h * 2 + 1]);
                }
                rmax[mi * 2 + h] = m;
            }
#pragma unroll
        for (int r = 0; r < 4; r++) {
            rmax[r] = fmaxf(rmax[r], __shfl_xor_sync(0xffffffffu, rmax[r], 1));
            rmax[r] = fmaxf(rmax[r], __shfl_xor_sync(0xffffffffu, rmax[r], 2));
        }
        if ((lane & 3) == 0) {
#pragma unroll
            for (int r = 0; r < 4; r++) {
                int rg = wm * 32 + (r >> 1) * 16 + row4 + (r & 1) * 8;
                red_m[rg * 2 + wn] = rmax[r];
            }
        }
        __syncthreads();

        float m_new[4], s_r[4];
#pragma unroll
        for (int r = 0; r < 4; r++) {
            int rg = wm * 32 + (r >> 1) * 16 + row4 + (r & 1) * 8;
            float tm = fmaxf(red_m[rg * 2], red_m[rg * 2 + 1]);
            m_new[r] = fmaxf(m_r[r], tm);
        }
#pragma unroll
        for (int mi = 0; mi < 2; mi++)
#pragma unroll
            for (int h = 0; h < 2; h++) {
                float mn = m_new[mi * 2 + h];
                float s = 0.0f;
#pragma unroll
                for (int ni = 0; ni < 8; ni++) {
                    s += __expf(acc[mi][ni][h * 2] - mn);
                    s += __expf(acc[mi][ni][h * 2 + 1] - mn);
                }
                s_r[mi * 2 + h] = s;
            }
#pragma unroll
        for (int r = 0; r < 4; r++) {
            s_r[r] += __shfl_xor_sync(0xffffffffu, s_r[r], 1);
            s_r[r] += __shfl_xor_sync(0xffffffffu, s_r[r], 2);
        }
        if ((lane & 3) == 0) {
#pragma unroll
            for (int r = 0; r < 4; r++) {
                int rg = wm * 32 + (r >> 1) * 16 + row4 + (r & 1) * 8;
                red_l[rg * 2 + wn] = s_r[r];
            }
        }
        if (kt == rb) {
#pragma unroll
            for (int mi = 0; mi < 2; mi++)
#pragma unroll
                for (int ni = 0; ni < 8; ni++)
#pragma unroll
                    for (int q = 0; q < 4; q++) {
                        int rl = wm * 32 + mi * 16 + row4 + (q >> 1) * 8;
                        int cl = wn * 64 + ni * 8 + (lane & 3) * 2 + (q & 1);
                        if (rl == cl) diag[rl] = acc[mi][ni][q];
                    }
        }
        __syncthreads();
#pragma unroll
        for (int r = 0; r < 4; r++) {
            int rg = wm * 32 + (r >> 1) * 16 + row4 + (r & 1) * 8;
            float ts = red_l[rg * 2] + red_l[rg * 2 + 1];
            l_r[r] = l_r[r] * __expf(m_r[r] - m_new[r]) + ts;
            m_r[r] = m_new[r];
        }
    }

    if (wn == 0 && (lane & 3) == 0) {
        float v = 0.0f;
#pragma unroll
        for (int r = 0; r < 4; r++) {
            int rg = wm * 32 + (r >> 1) * 16 + row4 + (r & 1) * 8;
            v += diag[rg] - (m_r[r] + logf(l_r[r]));
        }
        atomicAdd(&g_nce, v);
    }
}

// ---------------- BatchNorm statistics -------------------------------------
__global__ void bnstat_kernel()
{
    const int c   = blockIdx.x;
    const int tid = threadIdx.x;
    float s = 0.0f, sq = 0.0f;
    for (int b = tid; b < B_; b += 256) {
        float v = g_h[(size_t)b * C_ + c];
        s += v;
        sq = fmaf(v, v, sq);
    }
    __shared__ float ss[256], sqq[256];
    ss[tid] = s; sqq[tid] = sq;
    __syncthreads();
    for (int st = 128; st > 0; st >>= 1) {
        if (tid < st) { ss[tid] += ss[tid + st]; sqq[tid] += sqq[tid + st]; }
        __syncthreads();
    }
    if (tid == 0) {
        float mean = ss[0] * (1.0f / B_);
        float var  = sqq[0] * (1.0f / B_) - mean * mean;
        g_mean[c] = mean;
        g_rstd[c] = rsqrtf(var + 1e-5f);
    }
}

// ---------------- projection head ------------------------------------------
__global__ void proj_kernel(const float* __restrict__ gamma,
                            const float* __restrict__ beta,
                            const float* __restrict__ pw2,
                            const float* __restrict__ pb2,
                            float* __restrict__ out)
{
    __shared__ float w2s[P_][132];
    __shared__ float hn[32][129];
    __shared__ float mg[C_], bg[C_];

    const int tid  = threadIdx.x;
    const int base = blockIdx.x * 32;

    for (int f = tid; f < P_ * C_; f += 256) {
        int p = f >> 7, c = f & 127;
        w2s[p][c] = pw2[f];
    }
    if (tid < C_) {
        float sc = g_rstd[tid] * gamma[tid];
        mg[tid] = sc;
        bg[tid] = beta[tid] - g_mean[tid] * sc;
    }
    __syncthreads();

    for (int f = tid; f < 32 * C_; f += 256) {
        int r = f >> 7, c = f & 127;
        float v = g_h[(size_t)(base + r) * C_ + c];
        v = v * mg[c] + bg[c];
        v = (v >= 0.0f) ? v : 0.01f * v;
        hn[r][c] = v;
    }
    __syncthreads();

    const int r  = tid >> 3;
    const int pg = (tid & 7) * 4;
    float accp[4];
#pragma unroll
    for (int p = 0; p < 4; p++) accp[p] = 0.0f;
    for (int c = 0; c < C_; c++) {
        float hv = hn[r][c];
#pragma unroll
        for (int p = 0; p < 4; p++)
            accp[p] = fmaf(hv, w2s[pg + p][c], accp[p]);
    }
#pragma unroll
    for (int p = 0; p < 4; p++)
        out[1 + (size_t)(base + r) * P_ + pg + p] = accp[p] + pb2[pg + p];

    if (blockIdx.x == 0 && tid == 0)
        out[0] = g_nce * (-1.0f / (float)(B_ * T_));
}

// ---------------- launch ---------------------------------------------------
extern "C" void kernel_launch(void* const* d_in, const int* in_sizes, int n_in,
                              void* d_out, int out_size)
{
    const float* z     = (const float*)d_in[0];
    const float* c_t   = (const float*)d_in[1];
    const float* Wk_w  = (const float*)d_in[2];
    const float* Wk_b  = (const float*)d_in[3];
    const float* pw1   = (const float*)d_in[4];
    const float* pb1   = (const float*)d_in[5];
    const float* gamma = (const float*)d_in[6];
    const float* beta  = (const float*)d_in[7];
    const float* pw2   = (const float*)d_in[8];
    const float* pb2   = (const float*)d_in[9];
    float* out = (float*)d_out;

    init_kernel<<<(B_ * C_ + 255) / 256, 256>>>(z);
    convA_kernel<<<(B_ * D_ / 4) / 256, 256>>>(c_t);
    convW_kernel<<<(NT * C_ * D_ / 4) / 256, 256>>>(Wk_w, pw1);

    cudaFuncSetAttribute(gemm_mma_kernel,
                         cudaFuncAttributeMaxDynamicSharedMemorySize, GEMM_SMEM);
    gemm_mma_kernel<<<dim3(NT, 64), 256, GEMM_SMEM>>>();

    combine_kernel<<<NT * B_ * C_ / 4 / 256, 256>>>(Wk_b, pb1);

    cudaFuncSetAttribute(flash_mma_kernel,
                         cudaFuncAttributeMaxDynamicSharedMemorySize, FL_SMEM);
    flash_mma_kernel<<<dim3(B_ / 128, T_), 256, FL_SMEM>>>();

    bnstat_kernel<<<C_, 256>>>();
    proj_kernel<<<B_ / 32, 256>>>(gamma, beta, pw2, pb2, out);
}

// round 9
// speedup vs baseline: 3.2644x; 1.0302x over previous
#include <cuda_runtime.h>
#include <cuda_bf16.h>
#include <cstdint>

#define B_ 2048
#define T_ 18
#define C_ 128
#define D_ 4096
#define P_ 32
#define NT 19               // 18 timesteps + pw1 block
#define NC_ (D_ / 32)
#define NK64 64             // K-chunks of 64 bf16
#define AST_B 144           // gemm smem row stride (64 bf16 + 16B pad)
#define TILE_A (128 * AST_B)        // 18432
#define TILE_W (64 * AST_B)         // 9216
#define STAGE_SM (2 * TILE_A + 2 * TILE_W)   // 55296
#define GEMM_SMEM (2 * STAGE_SM)             // 110592
#define NUNITS 1216         // 19 t * 16 rt * 2 nh * 2 kh
#define NPCTAS 296

// ---------------- scratch (device globals; no allocation allowed) ----------
__device__ float g_h   [B_ * C_];
__device__ float g_mean[C_];
__device__ float g_rstd[C_];
__device__ float g_nce;
__device__ int   g_work;

// fp32 partial accumulators for the K-split GEMM: [t][b][c]
__device__ __align__(16) float g_acc0[NT * B_ * C_];
__device__ __align__(16) float g_acc1[NT * B_ * C_];

// bf16 hi/lo GEMM operand tiles: [rowtile/t][kc64][128 rows][64 cols]
__device__ __align__(16) __nv_bfloat16 g_Ahi[16 * NK64 * 8192];
__device__ __align__(16) __nv_bfloat16 g_Alo[16 * NK64 * 8192];
__device__ __align__(16) __nv_bfloat16 g_Whi[NT * NK64 * 8192];
__device__ __align__(16) __nv_bfloat16 g_Wlo[NT * NK64 * 8192];

// bf16 hi/lo enc + pred for flash: [t][b][c] row-major (C=128)
__device__ __align__(16) __nv_bfloat16 g_Ehi[T_ * B_ * C_];
__device__ __align__(16) __nv_bfloat16 g_Elo[T_ * B_ * C_];
__device__ __align__(16) __nv_bfloat16 g_Phi[T_ * B_ * C_];
__device__ __align__(16) __nv_bfloat16 g_Plo[T_ * B_ * C_];

// ---------------- helpers ---------------------------------------------------
__device__ __forceinline__ uint32_t smem_u32(const void* p) {
    uint32_t a;
    asm("{ .reg .u64 t; cvta.to.shared.u64 t, %1; cvt.u32.u64 %0, t; }"
        : "=r"(a) : "l"(p));
    return a;
}

__device__ __forceinline__ void cp16(uint32_t dst, const void* src) {
    asm volatile("cp.async.cg.shared.global [%0], [%1], 16;"
                 :: "r"(dst), "l"(src) : "memory");
}
#define CP_COMMIT() asm volatile("cp.async.commit_group;" ::: "memory")
#define CP_WAIT(N)  asm volatile("cp.async.wait_group %0;" :: "n"(N) : "memory")

__device__ __forceinline__ void ldmx4(uint32_t* r, uint32_t addr) {
    asm volatile("ldmatrix.sync.aligned.m8n8.x4.shared.b16 {%0,%1,%2,%3}, [%4];"
                 : "=r"(r[0]), "=r"(r[1]), "=r"(r[2]), "=r"(r[3]) : "r"(addr));
}

__device__ __forceinline__ void mma_bf16(float* c, const uint32_t* a,
                                         const uint32_t* b) {
    asm volatile(
        "mma.sync.aligned.m16n8k16.row.col.f32.bf16.bf16.f32 "
        "{%0,%1,%2,%3}, {%4,%5,%6,%7}, {%8,%9}, {%0,%1,%2,%3};"
        : "+f"(c[0]), "+f"(c[1]), "+f"(c[2]), "+f"(c[3])
        : "r"(a[0]), "r"(a[1]), "r"(a[2]), "r"(a[3]), "r"(b[0]), "r"(b[1]));
}

// ---------------- init: z_aug2 [B,C,T] -> Ehi/Elo [T,B,C]; zero nce/work ---
__global__ void init_kernel(const float* __restrict__ z)
{
    int bc = blockIdx.x * blockDim.x + threadIdx.x;
    if (bc == 0) { g_nce = 0.0f; g_work = 0; }
    if (bc < B_ * C_) {
        const float* src = z + (size_t)bc * T_;
#pragma unroll
        for (int t = 0; t < T_; t++) {
            float v = src[t];
            __nv_bfloat16 hi = __float2bfloat16(v);
            __nv_bfloat16 lo = __float2bfloat16(v - __bfloat162float(hi));
            g_Ehi[(size_t)t * B_ * C_ + bc] = hi;
            g_Elo[(size_t)t * B_ * C_ + bc] = lo;
        }
    }
}

// ---------------- pack A (c_t) into bf16 hi/lo GEMM tiles -------------------
__global__ void convA_kernel(const float* __restrict__ A)
{
    int i  = blockIdx.x * 256 + threadIdx.x;
    int gr = i >> 10;
    int k4 = (i & 1023) << 2;
    float4 v = *(const float4*)(A + (size_t)gr * D_ + k4);
    float f[4] = {v.x, v.y, v.z, v.w};
    __nv_bfloat162 h0, h1, l0, l1;
    {
        __nv_bfloat16 hi[4], lo[4];
#pragma unroll
        for (int j = 0; j < 4; j++) {
            hi[j] = __float2bfloat16(f[j]);
            lo[j] = __float2bfloat16(f[j] - __bfloat162float(hi[j]));
        }
        h0.x = hi[0]; h0.y = hi[1]; h1.x = hi[2]; h1.y = hi[3];
        l0.x = lo[0]; l0.y = lo[1]; l1.x = lo[2]; l1.y = lo[3];
    }
    int rt = gr >> 7, row = gr & 127, kc = k4 >> 6, col = k4 & 63;
    size_t off = (((size_t)(rt * NK64 + kc) * 128) + row) * 64 + col;
    *(__nv_bfloat162*)(g_Ahi + off)     = h0;
    *(__nv_bfloat162*)(g_Ahi + off + 2) = h1;
    *(__nv_bfloat162*)(g_Alo + off)     = l0;
    *(__nv_bfloat162*)(g_Alo + off + 2) = l1;
}

// ---------------- pack W (Wk_w + pw1) into bf16 hi/lo GEMM tiles ------------
__global__ void convW_kernel(const float* __restrict__ Wk_w,
                             const float* __restrict__ pw1)
{
    int i  = blockIdx.x * 256 + threadIdx.x;
    int rw = i >> 10;
    int k4 = (i & 1023) << 2;
    int t = rw >> 7, n = rw & 127;
    const float* src = (t < T_) ? (Wk_w + ((size_t)t * C_ + n) * D_ + k4)
                                : (pw1 + (size_t)n * D_ + k4);
    float4 v = *(const float4*)src;
    float f[4] = {v.x, v.y, v.z, v.w};
    __nv_bfloat162 h0, h1, l0, l1;
    {
        __nv_bfloat16 hi[4], lo[4];
#pragma unroll
        for (int j = 0; j < 4; j++) {
            hi[j] = __float2bfloat16(f[j]);
            lo[j] = __float2bfloat16(f[j] - __bfloat162float(hi[j]));
        }
        h0.x = hi[0]; h0.y = hi[1]; h1.x = hi[2]; h1.y = hi[3];
        l0.x = lo[0]; l0.y = lo[1]; l1.x = lo[2]; l1.y = lo[3];
    }
    int kc = k4 >> 6, col = k4 & 63;
    size_t off = (((size_t)(t * NK64 + kc) * 128) + n) * 64 + col;
    *(__nv_bfloat162*)(g_Whi + off)     = h0;
    *(__nv_bfloat162*)(g_Whi + off + 2) = h1;
    *(__nv_bfloat162*)(g_Wlo + off)     = l0;
    *(__nv_bfloat162*)(g_Wlo + off + 2) = l1;
}

// ---------------- persistent mma.sync GEMM, dynamic units -------------------
// unit u: tb = u>>6; r6 = u&63: kh = r6&1, nh = (r6>>1)&1, rt = r6>>2
// Each unit: C[128x64], K in [kh*2048, +2048), chunks of 64, 2-stage cp.async.
// Partials -> g_acc0/g_acc1 (disjoint, deterministic). 2 CTAs/SM.
__global__ __launch_bounds__(256, 2) void gemm_mma_kernel()
{
    extern __shared__ __align__(128) char smem[];
    const uint32_t sb0 = smem_u32(smem);
    __shared__ int s_u;

    const int tid  = threadIdx.x;
    const int lane = tid & 31, wid = tid >> 5;
    const int wm = wid >> 1, wn = wid & 1;

    const int a_r  = wm * 32 + (lane & 15);
    const int a_kb = (lane >> 4) << 4;
    const int w_r  = wn * 32 + (lane & 7) + ((lane >> 4) << 3);
    const int w_kb = ((lane >> 3) & 1) << 4;

    const int u_row = tid >> 3;          // 0..31 (A: +32*j; W: +32*j)
    const int u_c   = (tid & 7) << 4;    // 0..112

    for (;;) {
        __syncthreads();
        if (tid == 0) s_u = atomicAdd(&g_work, 1);
        __syncthreads();
        const int u = s_u;
        if (u >= NUNITS) break;

        const int tb = u >> 6;
        const int r6 = u & 63;
        const int kh = r6 & 1;
        const int nh = (r6 >> 1) & 1;
        const int rt = r6 >> 2;
        const int kc0 = kh * 32;

        float acc[2][4][4];
#pragma unroll
        for (int mi = 0; mi < 2; mi++)
#pragma unroll
            for (int ni = 0; ni < 4; ni++)
#pragma unroll
                for (int q = 0; q < 4; q++) acc[mi][ni][q] = 0.0f;

#define GEMM_LOADS(stage_base, kcg)                                           \
    do {                                                                      \
        const char* Ah = (const char*)g_Ahi + (((size_t)(rt * NK64 + (kcg))) << 14); \
        const char* Al = (const char*)g_Alo + (((size_t)(rt * NK64 + (kcg))) << 14); \
        const char* Wh = (const char*)g_Whi + (((size_t)(tb * NK64 + (kcg))) << 14) + nh * 8192; \
        const char* Wl = (const char*)g_Wlo + (((size_t)(tb * NK64 + (kcg))) << 14) + nh * 8192; \
        _Pragma("unroll")                                                     \
        for (int j = 0; j < 4; j++) {                                         \
            int row = u_row + j * 32;                                         \
            cp16((stage_base) + row * AST_B + u_c, Ah + row * 128 + u_c);     \
            cp16((stage_base) + TILE_A + row * AST_B + u_c,                   \
                 Al + row * 128 + u_c);                                       \
        }                                                                     \
        _Pragma("unroll")                                                     \
        for (int j = 0; j < 2; j++) {                                         \
            int row = u_row + j * 32;                                         \
            cp16((stage_base) + 2 * TILE_A + row * AST_B + u_c,               \
                 Wh + row * 128 + u_c);                                       \
            cp16((stage_base) + 2 * TILE_A + TILE_W + row * AST_B + u_c,      \
                 Wl + row * 128 + u_c);                                       \
        }                                                                     \
    } while (0)

        GEMM_LOADS(sb0, kc0);
        CP_COMMIT();

        for (int kc = 0; kc < 32; kc++) {
            if (kc + 1 < 32) {
                uint32_t sb = sb0 + ((kc + 1) & 1) * STAGE_SM;
                GEMM_LOADS(sb, kc0 + kc + 1);
                CP_COMMIT();
                CP_WAIT(1);
            } else {
                CP_WAIT(0);
            }
            __syncthreads();

            const uint32_t st = sb0 + (kc & 1) * STAGE_SM;
            const uint32_t Ahi_b = st, Alo_b = st + TILE_A;
            const uint32_t Whi_b = st + 2 * TILE_A;
            const uint32_t Wlo_b = st + 2 * TILE_A + TILE_W;
#pragma unroll
            for (int k16 = 0; k16 < 4; k16++) {
                uint32_t bh[8], bl[8];
                ldmx4(bh,     Whi_b + (w_r)      * AST_B + k16 * 32 + w_kb);
                ldmx4(bh + 4, Whi_b + (w_r + 16) * AST_B + k16 * 32 + w_kb);
                ldmx4(bl,     Wlo_b + (w_r)      * AST_B + k16 * 32 + w_kb);
                ldmx4(bl + 4, Wlo_b + (w_r + 16) * AST_B + k16 * 32 + w_kb);
#pragma unroll
                for (int mi = 0; mi < 2; mi++) {
                    uint32_t a[4];
                    ldmx4(a, Ahi_b + (a_r + mi * 16) * AST_B + k16 * 32 + a_kb);
#pragma unroll
                    for (int ni = 0; ni < 4; ni++) mma_bf16(acc[mi][ni], a, bh + ni * 2);
#pragma unroll
                    for (int ni = 0; ni < 4; ni++) mma_bf16(acc[mi][ni], a, bl + ni * 2);
                }
#pragma unroll
                for (int mi = 0; mi < 2; mi++) {
                    uint32_t a[4];
                    ldmx4(a, Alo_b + (a_r + mi * 16) * AST_B + k16 * 32 + a_kb);
#pragma unroll
                    for (int ni = 0; ni < 4; ni++) mma_bf16(acc[mi][ni], a, bh + ni * 2);
                }
            }
            __syncthreads();
        }

        // ---- epilogue: fp32 partial store (disjoint per kh) ----
        float* outp = (kh ? g_acc1 : g_acc0) + (size_t)tb * B_ * C_;
        const int r0 = rt * 128 + wm * 32 + (lane >> 2);
        const int c0 = nh * 64 + wn * 32 + (lane & 3) * 2;
#pragma unroll
        for (int mi = 0; mi < 2; mi++)
#pragma unroll
            for (int ni = 0; ni < 4; ni++) {
                int row = r0 + mi * 16, col = c0 + ni * 8;
                float2 v;
                v.x = acc[mi][ni][0]; v.y = acc[mi][ni][1];
                *(float2*)(outp + (size_t)row * C_ + col) = v;
                v.x = acc[mi][ni][2]; v.y = acc[mi][ni][3];
                *(float2*)(outp + (size_t)(row + 8) * C_ + col) = v;
            }
#undef GEMM_LOADS
    }
}

// ---------------- combine: acc0+acc1+bias -> Phi/Plo (t<18) or g_h ---------
__global__ void combine_kernel(const float* __restrict__ Wk_b,
                               const float* __restrict__ pb1)
{
    const int per_t = B_ * C_ / 4;
    int i = blockIdx.x * 256 + threadIdx.x;
    int t = i / per_t;
    int r = i - t * per_t;
    int c = (r & 31) << 2;

    const float4 v0 = *((const float4*)g_acc0 + i);
    const float4 v1 = *((const float4*)g_acc1 + i);
    const float* bias = (t < T_) ? (Wk_b + t * C_) : pb1;
    float s[4];
    s[0] = v0.x + v1.x + __ldg(bias + c + 0);
    s[1] = v0.y + v1.y + __ldg(bias + c + 1);
    s[2] = v0.z + v1.z + __ldg(bias + c + 2);
    s[3] = v0.w + v1.w + __ldg(bias + c + 3);

    if (t < T_) {
        __nv_bfloat162 h0, h1, l0, l1;
        h0.x = __float2bfloat16(s[0]);
        l0.x = __float2bfloat16(s[0] - __bfloat162float(h0.x));
        h0.y = __float2bfloat16(s[1]);
        l0.y = __float2bfloat16(s[1] - __bfloat162float(h0.y));
        h1.x = __float2bfloat16(s[2]);
        l1.x = __float2bfloat16(s[2] - __bfloat162float(h1.x));
        h1.y = __float2bfloat16(s[3]);
        l1.y = __float2bfloat16(s[3] - __bfloat162float(h1.y));
        size_t off = (size_t)t * B_ * C_ + (size_t)r * 4;
        *(__nv_bfloat162*)(g_Phi + off)     = h0;
        *(__nv_bfloat162*)(g_Phi + off + 2) = h1;
        *(__nv_bfloat162*)(g_Plo + off)     = l0;
        *(__nv_bfloat162*)(g_Plo + off + 2) = l1;
    } else {
        float4 o; o.x = s[0]; o.y = s[1]; o.z = s[2]; o.w = s[3];
        *((float4*)g_h + r) = o;
    }
}

// ---------------- flash NCE via mma.sync: block = 128 q-rows x t -----------
#define FST 272                     // 128 bf16 + 16B pad
#define FTILE_ (128 * FST)          // 34816
#define FL_REDM (6 * FTILE_)
#define FL_REDL (FL_REDM + 1024)
#define FL_DIAG (FL_REDL + 1024)
#define FL_SMEM (FL_DIAG + 512)     // 211456 bytes

__global__ __launch_bounds__(256, 1) void flash_mma_kernel()
{
    extern __shared__ __align__(128) char smem[];
    const uint32_t sb = smem_u32(smem);
    float* red_m = (float*)(smem + FL_REDM);
    float* red_l = (float*)(smem + FL_REDL);
    float* diag  = (float*)(smem + FL_DIAG);

    const int rb = blockIdx.x, t = blockIdx.y;
    const int tid = threadIdx.x, lane = tid & 31, wid = tid >> 5;
    const int wm = wid >> 1, wn = wid & 1;      // warp tile 32 x 64

    const __nv_bfloat16* Ehi = g_Ehi + ((size_t)t * B_ + rb * 128) * C_;
    const __nv_bfloat16* Elo = g_Elo + ((size_t)t * B_ + rb * 128) * C_;
    const __nv_bfloat16* Phi = g_Phi + (size_t)t * B_ * C_;
    const __nv_bfloat16* Plo = g_Plo + (size_t)t * B_ * C_;

#pragma unroll
    for (int f = 0; f < 8; f++) {
        int id = tid + f * 256, r = id >> 4, ch = (id & 15) << 4;
        cp16(sb + r * FST + ch,          (const char*)Ehi + r * 256 + ch);
        cp16(sb + FTILE_ + r * FST + ch, (const char*)Elo + r * 256 + ch);
    }
    CP_COMMIT();
#pragma unroll
    for (int f = 0; f < 8; f++) {
        int id = tid + f * 256, r = id >> 4, ch = (id & 15) << 4;
        cp16(sb + 2 * FTILE_ + r * FST + ch, (const char*)Phi + r * 256 + ch);
        cp16(sb + 3 * FTILE_ + r * FST + ch, (const char*)Plo + r * 256 + ch);
    }
    CP_COMMIT();

    float m_r[4], l_r[4];
#pragma unroll
    for (int r = 0; r < 4; r++) { m_r[r] = -3.0e38f; l_r[r] = 0.0f; }

    const int a_rr = wm * 32 + (lane & 15);
    const int a_kb = (lane >> 4) << 4;
    const int b_rr = wn * 64 + (lane & 7) + ((lane >> 4) << 3);
    const int b_kb = ((lane >> 3) & 1) << 4;
    const int row4 = lane >> 2;

    for (int kt = 0; kt < 16; kt++) {
        if (kt + 1 < 16) {
            uint32_t kb = sb + (2 + ((kt + 1) & 1) * 2) * FTILE_;
            const char* sh = (const char*)Phi + (size_t)(kt + 1) * 128 * 256;
            const char* sl = (const char*)Plo + (size_t)(kt + 1) * 128 * 256;
#pragma unroll
            for (int f = 0; f < 8; f++) {
                int id = tid + f * 256, r = id >> 4, ch = (id & 15) << 4;
                cp16(kb + r * FST + ch,          sh + r * 256 + ch);
                cp16(kb + FTILE_ + r * FST + ch, sl + r * 256 + ch);
            }
            CP_COMMIT();
            CP_WAIT(1);
        } else {
            CP_WAIT(0);
        }
        __syncthreads();

        const uint32_t Qh = sb, Ql = sb + FTILE_;
        const uint32_t Kh = sb + (2 + (kt & 1) * 2) * FTILE_;
        const uint32_t Kl = Kh + FTILE_;

        float acc[2][8][4];
#pragma unroll
        for (int mi = 0; mi < 2; mi++)
#pragma unroll
            for (int ni = 0; ni < 8; ni++)
#pragma unroll
                for (int q = 0; q < 4; q++) acc[mi][ni][q] = 0.0f;

#pragma unroll
        for (int k16 = 0; k16 < 8; k16++) {
            uint32_t bh[16], bl[16];
#pragma unroll
            for (int g = 0; g < 4; g++) {
                ldmx4(bh + g * 4, Kh + (b_rr + g * 16) * FST + k16 * 32 + b_kb);
                ldmx4(bl + g * 4, Kl + (b_rr + g * 16) * FST + k16 * 32 + b_kb);
            }
#pragma unroll
            for (int mi = 0; mi < 2; mi++) {
                uint32_t a[4];
                ldmx4(a, Qh + (a_rr + mi * 16) * FST + k16 * 32 + a_kb);
#pragma unroll
                for (int ni = 0; ni < 8; ni++) mma_bf16(acc[mi][ni], a, bh + ni * 2);
#pragma unroll
                for (int ni = 0; ni < 8; ni++) mma_bf16(acc[mi][ni], a, bl + ni * 2);
            }
#pragma unroll
            for (int mi = 0; mi < 2; mi++) {
                uint32_t a[4];
                ldmx4(a, Ql + (a_rr + mi * 16) * FST + k16 * 32 + a_kb);
#pragma unroll
                for (int ni = 0; ni < 8; ni++) mma_bf16(acc[mi][ni], a, bh + ni * 2);
            }
        }

        float rmax[4];
#pragma unroll
        for (int mi = 0; mi < 2; mi++)
#pragma unroll
            for (int h = 0; h < 2; h++) {
                float m = acc[mi][0][h * 2];
#pragma unroll
                for (int ni = 0; ni < 8; ni++) {
                    m = fmaxf(m, acc[mi][ni][h * 2]);
                    m = fmaxf(m, acc[mi][ni][h * 2 + 1]);
                }
                rmax[mi * 2 + h] = m;
            }
#pragma unroll
        for (int r = 0; r < 4; r++) {
            rmax[r] = fmaxf(rmax[r], __shfl_xor_sync(0xffffffffu, rmax[r], 1));
            rmax[r] = fmaxf(rmax[r], __shfl_xor_sync(0xffffffffu, rmax[r], 2));
        }
        if ((lane & 3) == 0) {
#pragma unroll
            for (int r = 0; r < 4; r++) {
                int rg = wm * 32 + (r >> 1) * 16 + row4 + (r & 1) * 8;
                red_m[rg * 2 + wn] = rmax[r];
            }
        }
        __syncthreads();

        float m_new[4], s_r[4];
#pragma unroll
        for (int r = 0; r < 4; r++) {
            int rg = wm * 32 + (r >> 1) * 16 + row4 + (r & 1) * 8;
            float tm = fmaxf(red_m[rg * 2], red_m[rg * 2 + 1]);
            m_new[r] = fmaxf(m_r[r], tm);
        }
#pragma unroll
        for (int mi = 0; mi < 2; mi++)
#pragma unroll
            for (int h = 0; h < 2; h++) {
                float mn = m_new[mi * 2 + h];
                float s = 0.0f;
#pragma unroll
                for (int ni = 0; ni < 8; ni++) {
                    s += __expf(acc[mi][ni][h * 2] - mn);
                    s += __expf(acc[mi][ni][h * 2 + 1] - mn);
                }
                s_r[mi * 2 + h] = s;
            }
#pragma unroll
        for (int r = 0; r < 4; r++) {
            s_r[r] += __shfl_xor_sync(0xffffffffu, s_r[r], 1);
            s_r[r] += __shfl_xor_sync(0xffffffffu, s_r[r], 2);
        }
        if ((lane & 3) == 0) {
#pragma unroll
            for (int r = 0; r < 4; r++) {
                int rg = wm * 32 + (r >> 1) * 16 + row4 + (r & 1) * 8;
                red_l[rg * 2 + wn] = s_r[r];
            }
        }
        if (kt == rb) {
#pragma unroll
            for (int mi = 0; mi < 2; mi++)
#pragma unroll
                for (int ni = 0; ni < 8; ni++)
#pragma unroll
                    for (int q = 0; q < 4; q++) {
                        int rl = wm * 32 + mi * 16 + row4 + (q >> 1) * 8;
                        int cl = wn * 64 + ni * 8 + (lane & 3) * 2 + (q & 1);
                        if (rl == cl) diag[rl] = acc[mi][ni][q];
                    }
        }
        __syncthreads();
#pragma unroll
        for (int r = 0; r < 4; r++) {
            int rg = wm * 32 + (r >> 1) * 16 + row4 + (r & 1) * 8;
            float ts = red_l[rg * 2] + red_l[rg * 2 + 1];
            l_r[r] = l_r[r] * __expf(m_r[r] - m_new[r]) + ts;
            m_r[r] = m_new[r];
        }
    }

    if (wn == 0 && (lane & 3) == 0) {
        float v = 0.0f;
#pragma unroll
        for (int r = 0; r < 4; r++) {
            int rg = wm * 32 + (r >> 1) * 16 + row4 + (r & 1) * 8;
            v += diag[rg] - (m_r[r] + logf(l_r[r]));
        }
        atomicAdd(&g_nce, v);
    }
}

// ---------------- BatchNorm statistics -------------------------------------
__global__ void bnstat_kernel()
{
    const int c   = blockIdx.x;
    const int tid = threadIdx.x;
    float s = 0.0f, sq = 0.0f;
    for (int b = tid; b < B_; b += 256) {
        float v = g_h[(size_t)b * C_ + c];
        s += v;
        sq = fmaf(v, v, sq);
    }
    __shared__ float ss[256], sqq[256];
    ss[tid] = s; sqq[tid] = sq;
    __syncthreads();
    for (int st = 128; st > 0; st >>= 1) {
        if (tid < st) { ss[tid] += ss[tid + st]; sqq[tid] += sqq[tid + st]; }
        __syncthreads();
    }
    if (tid == 0) {
        float mean = ss[0] * (1.0f / B_);
        float var  = sqq[0] * (1.0f / B_) - mean * mean;
        g_mean[c] = mean;
        g_rstd[c] = rsqrtf(var + 1e-5f);
    }
}

// ---------------- projection head ------------------------------------------
__global__ void proj_kernel(const float* __restrict__ gamma,
                            const float* __restrict__ beta,
                            const float* __restrict__ pw2,
                            const float* __restrict__ pb2,
                            float* __restrict__ out)
{
    __shared__ float w2s[P_][132];
    __shared__ float hn[32][129];
    __shared__ float mg[C_], bg[C_];

    const int tid  = threadIdx.x;
    const int base = blockIdx.x * 32;

    for (int f = tid; f < P_ * C_; f += 256) {
        int p = f >> 7, c = f & 127;
        w2s[p][c] = pw2[f];
    }
    if (tid < C_) {
        float sc = g_rstd[tid] * gamma[tid];
        mg[tid] = sc;
        bg[tid] = beta[tid] - g_mean[tid] * sc;
    }
    __syncthreads();

    for (int f = tid; f < 32 * C_; f += 256) {
        int r = f >> 7, c = f & 127;
        float v = g_h[(size_t)(base + r) * C_ + c];
        v = v * mg[c] + bg[c];
        v = (v >= 0.0f) ? v : 0.01f * v;
        hn[r][c] = v;
    }
    __syncthreads();

    const int r  = tid >> 3;
    const int pg = (tid & 7) * 4;
    float accp[4];
#pragma unroll
    for (int p = 0; p < 4; p++) accp[p] = 0.0f;
    for (int c = 0; c < C_; c++) {
        float hv = hn[r][c];
#pragma unroll
        for (int p = 0; p < 4; p++)
            accp[p] = fmaf(hv, w2s[pg + p][c], accp[p]);
    }
#pragma unroll
    for (int p = 0; p < 4; p++)
        out[1 + (size_t)(base + r) * P_ + pg + p] = accp[p] + pb2[pg + p];

    if (blockIdx.x == 0 && tid == 0)
        out[0] = g_nce * (-1.0f / (float)(B_ * T_));
}

// ---------------- launch ---------------------------------------------------
extern "C" void kernel_launch(void* const* d_in, const int* in_sizes, int n_in,
                              void* d_out, int out_size)
{
    const float* z     = (const float*)d_in[0];
    const float* c_t   = (const float*)d_in[1];
    const float* Wk_w  = (const float*)d_in[2];
    const float* Wk_b  = (const float*)d_in[3];
    const float* pw1   = (const float*)d_in[4];
    const float* pb1   = (const float*)d_in[5];
    const float* gamma = (const float*)d_in[6];
    const float* beta  = (const float*)d_in[7];
    const float* pw2   = (const float*)d_in[8];
    const float* pb2   = (const float*)d_in[9];
    float* out = (float*)d_out;

    init_kernel<<<(B_ * C_ + 255) / 256, 256>>>(z);
    convA_kernel<<<(B_ * D_ / 4) / 256, 256>>>(c_t);
    convW_kernel<<<(NT * C_ * D_ / 4) / 256, 256>>>(Wk_w, pw1);

    cudaFuncSetAttribute(gemm_mma_kernel,
                         cudaFuncAttributeMaxDynamicSharedMemorySize, GEMM_SMEM);
    gemm_mma_kernel<<<NPCTAS, 256, GEMM_SMEM>>>();

    combine_kernel<<<NT * B_ * C_ / 4 / 256, 256>>>(Wk_b, pb1);

    cudaFuncSetAttribute(flash_mma_kernel,
                         cudaFuncAttributeMaxDynamicSharedMemorySize, FL_SMEM);
    flash_mma_kernel<<<dim3(B_ / 128, T_), 256, FL_SMEM>>>();

    bnstat_kernel<<<C_, 256>>>();
    proj_kernel<<<B_ / 32, 256>>>(gamma, beta, pw2, pb2, out);
}

// round 10
// speedup vs baseline: 3.9889x; 1.2220x over previous
#include <cuda_runtime.h>
#include <cuda_bf16.h>
#include <cstdint>

#define B_ 2048
#define T_ 18
#define C_ 128
#define D_ 4096
#define P_ 32
#define NT 19               // 18 timesteps + pw1 block
#define NUNITS 1216         // 19 t * 16 rt * 2 nh * 2 kh
#define NPCTAS 296

// ---------------- scratch (device globals; no allocation allowed) ----------
__device__ float g_h   [B_ * C_];
__device__ float g_mean[C_];
__device__ float g_rstd[C_];
__device__ float g_nce;
__device__ int   g_work;

// fp32 partial accumulators for the K-split GEMM: [t][b][c]
__device__ __align__(16) float g_acc0[NT * B_ * C_];
__device__ __align__(16) float g_acc1[NT * B_ * C_];

// mma-fragment-packed operands.
// A: [rt 0..15][k16 0..255][m16 0..7][lane 0..31] -> uint4 (a0,a1,a2,a3)
// W: [t 0..18][k16 0..255][n16grp 0..7][lane]     -> uint4 (blk0 b0,b1, blk1 b0,b1)
__device__ __align__(16) uint4 g_Afh[16 * 256 * 8 * 32];
__device__ __align__(16) uint4 g_Afl[16 * 256 * 8 * 32];
__device__ __align__(16) uint4 g_Wfh[NT * 256 * 8 * 32];
__device__ __align__(16) uint4 g_Wfl[NT * 256 * 8 * 32];

// bf16 hi/lo enc + pred for flash: [t][b][c] row-major (C=128)
__device__ __align__(16) __nv_bfloat16 g_Ehi[T_ * B_ * C_];
__device__ __align__(16) __nv_bfloat16 g_Elo[T_ * B_ * C_];
__device__ __align__(16) __nv_bfloat16 g_Phi[T_ * B_ * C_];
__device__ __align__(16) __nv_bfloat16 g_Plo[T_ * B_ * C_];

// ---------------- helpers ---------------------------------------------------
__device__ __forceinline__ uint32_t smem_u32(const void* p) {
    uint32_t a;
    asm("{ .reg .u64 t; cvta.to.shared.u64 t, %1; cvt.u32.u64 %0, t; }"
        : "=r"(a) : "l"(p));
    return a;
}

__device__ __forceinline__ void cp16(uint32_t dst, const void* src) {
    asm volatile("cp.async.cg.shared.global [%0], [%1], 16;"
                 :: "r"(dst), "l"(src) : "memory");
}
#define CP_COMMIT() asm volatile("cp.async.commit_group;" ::: "memory")
#define CP_WAIT(N)  asm volatile("cp.async.wait_group %0;" :: "n"(N) : "memory")

__device__ __forceinline__ void ldmx4(uint32_t* r, uint32_t addr) {
    asm volatile("ldmatrix.sync.aligned.m8n8.x4.shared.b16 {%0,%1,%2,%3}, [%4];"
                 : "=r"(r[0]), "=r"(r[1]), "=r"(r[2]), "=r"(r[3]) : "r"(addr));
}

__device__ __forceinline__ void mma_bf16(float* c, const uint32_t* a,
                                         const uint32_t* b) {
    asm volatile(
        "mma.sync.aligned.m16n8k16.row.col.f32.bf16.bf16.f32 "
        "{%0,%1,%2,%3}, {%4,%5,%6,%7}, {%8,%9}, {%0,%1,%2,%3};"
        : "+f"(c[0]), "+f"(c[1]), "+f"(c[2]), "+f"(c[3])
        : "r"(a[0]), "r"(a[1]), "r"(a[2]), "r"(a[3]), "r"(b[0]), "r"(b[1]));
}

__device__ __forceinline__ uint32_t pack_bf16(float x, float y) {
    __nv_bfloat162 v;
    v.x = __float2bfloat16(x);
    v.y = __float2bfloat16(y);
    return *(uint32_t*)&v;
}
__device__ __forceinline__ void hilo_pack(float x, float y,
                                          uint32_t& h, uint32_t& l) {
    __nv_bfloat16 hx = __float2bfloat16(x);
    __nv_bfloat16 hy = __float2bfloat16(y);
    h = pack_bf16(x, y);
    l = pack_bf16(x - __bfloat162float(hx), y - __bfloat162float(hy));
}

// ---------------- init: z_aug2 [B,C,T] -> Ehi/Elo [T,B,C]; zero nce/work ---
__global__ void init_kernel(const float* __restrict__ z)
{
    int bc = blockIdx.x * blockDim.x + threadIdx.x;
    if (bc == 0) { g_nce = 0.0f; g_work = 0; }
    if (bc < B_ * C_) {
        const float* src = z + (size_t)bc * T_;
#pragma unroll
        for (int t = 0; t < T_; t++) {
            float v = src[t];
            __nv_bfloat16 hi = __float2bfloat16(v);
            __nv_bfloat16 lo = __float2bfloat16(v - __bfloat162float(hi));
            g_Ehi[(size_t)t * B_ * C_ + bc] = hi;
            g_Elo[(size_t)t * B_ * C_ + bc] = lo;
        }
    }
}

// ---------------- pack A (c_t) into mma A-fragment layout -------------------
// block b = rt*2048 + kg*8 + mi; lane l:
//  a0 = A[row][k..k+1], a1 = A[row+8][k..k+1], a2 = A[row][k+8..k+9], a3 = row+8,k+8
//  row = rt*128 + mi*16 + (l>>2);  k = kg*16 + (l&3)*2
__global__ void convA_kernel(const float* __restrict__ A)
{
    int id = blockIdx.x * 256 + threadIdx.x;      // 0 .. 1048575
    int lane = id & 31;
    int b = id >> 5;                               // 0 .. 32767
    int mi = b & 7, kg = (b >> 3) & 255, rt = b >> 11;
    int row = rt * 128 + mi * 16 + (lane >> 2);
    int k   = kg * 16 + (lane & 3) * 2;

    const float* r0 = A + (size_t)row * D_ + k;
    const float* r1 = r0 + 8 * D_;
    uint4 h, l;
    hilo_pack(r0[0], r0[1], h.x, l.x);
    hilo_pack(r1[0], r1[1], h.y, l.y);
    hilo_pack(r0[8], r0[9], h.z, l.z);
    hilo_pack(r1[8], r1[9], h.w, l.w);
    g_Afh[(size_t)b * 32 + lane] = h;
    g_Afl[(size_t)b * 32 + lane] = l;
}

// ---------------- pack W (Wk_w + pw1) into mma B-fragment layout ------------
// block b = t*2048 + kg*8 + g; lane l:
//  j0 = W[n0][k..k+1], j1 = W[n0][k+8..k+9], j2 = W[n0+8][k..], j3 = W[n0+8][k+8..]
//  n0 = g*16 + (l>>2);  k = kg*16 + (l&3)*2
__global__ void convW_kernel(const float* __restrict__ Wk_w,
                             const float* __restrict__ pw1)
{
    int id = blockIdx.x * 256 + threadIdx.x;      // 0 .. 1245183
    int lane = id & 31;
    int b = id >> 5;                               // 0 .. 38911
    int g = b & 7, kg = (b >> 3) & 255, t = b >> 11;
    int n0 = g * 16 + (lane >> 2);
    int k  = kg * 16 + (lane & 3) * 2;

    const float* s0 = (t < T_) ? (Wk_w + ((size_t)t * C_ + n0) * D_ + k)
                               : (pw1 + (size_t)n0 * D_ + k);
    const float* s1 = s0 + 8 * D_;
    uint4 h, l;
    hilo_pack(s0[0], s0[1], h.x, l.x);
    hilo_pack(s0[8], s0[9], h.y, l.y);
    hilo_pack(s1[0], s1[1], h.z, l.z);
    hilo_pack(s1[8], s1[9], h.w, l.w);
    g_Wfh[(size_t)b * 32 + lane] = h;
    g_Wfl[(size_t)b * 32 + lane] = l;
}

// ---------------- persistent mma.sync GEMM, fragments direct from L2 -------
// unit u: tb = u>>6; r6 = u&63: kh = r6&1, nh = (r6>>1)&1, rt = r6>>2
// C[128x64] per unit, K in [kh*2048,+2048) = 128 k16 steps. No smem mainloop,
// no barriers: warps free-run; fragments via LDG.128 (L2-resident pool).
__global__ __launch_bounds__(256, 2) void gemm_mma_kernel()
{
    __shared__ int s_u;
    const int tid = threadIdx.x;
    const int lane = tid & 31, wid = tid >> 5;
    const int wm = wid >> 1, wn = wid & 1;     // warp tile 32x32

    for (;;) {
        __syncthreads();
        if (tid == 0) s_u = atomicAdd(&g_work, 1);
        __syncthreads();
        const int u = s_u;
        if (u >= NUNITS) break;

        const int tb = u >> 6;
        const int r6 = u & 63;
        const int kh = r6 & 1;
        const int nh = (r6 >> 1) & 1;
        const int rt = r6 >> 2;

        float acc[2][4][4];
#pragma unroll
        for (int mi = 0; mi < 2; mi++)
#pragma unroll
            for (int ni = 0; ni < 4; ni++)
#pragma unroll
                for (int q = 0; q < 4; q++) acc[mi][ni][q] = 0.0f;

        const uint4* pAh = g_Afh +
            ((size_t)(rt * 256 + kh * 128) * 8 + 2 * wm) * 32 + lane;
        const uint4* pAl = g_Afl +
            ((size_t)(rt * 256 + kh * 128) * 8 + 2 * wm) * 32 + lane;
        const uint4* pWh = g_Wfh +
            ((size_t)(tb * 256 + kh * 128) * 8 + nh * 4 + wn * 2) * 32 + lane;
        const uint4* pWl = g_Wfl +
            ((size_t)(tb * 256 + kh * 128) * 8 + nh * 4 + wn * 2) * 32 + lane;

#pragma unroll 2
        for (int kg = 0; kg < 128; kg++) {
            uint32_t ah[8], al[8], wh[8], wl[8];
            {
                uint4 v;
                v = pAh[0];  ah[0] = v.x; ah[1] = v.y; ah[2] = v.z; ah[3] = v.w;
                v = pAh[32]; ah[4] = v.x; ah[5] = v.y; ah[6] = v.z; ah[7] = v.w;
                v = pAl[0];  al[0] = v.x; al[1] = v.y; al[2] = v.z; al[3] = v.w;
                v = pAl[32]; al[4] = v.x; al[5] = v.y; al[6] = v.z; al[7] = v.w;
                v = pWh[0];  wh[0] = v.x; wh[1] = v.y; wh[2] = v.z; wh[3] = v.w;
                v = pWh[32]; wh[4] = v.x; wh[5] = v.y; wh[6] = v.z; wh[7] = v.w;
                v = pWl[0];  wl[0] = v.x; wl[1] = v.y; wl[2] = v.z; wl[3] = v.w;
                v = pWl[32]; wl[4] = v.x; wl[5] = v.y; wl[6] = v.z; wl[7] = v.w;
            }
            pAh += 256; pAl += 256; pWh += 256; pWl += 256;

#pragma unroll
            for (int mi = 0; mi < 2; mi++) {
#pragma unroll
                for (int ni = 0; ni < 4; ni++)
                    mma_bf16(acc[mi][ni], ah + mi * 4, wh + ni * 2);
#pragma unroll
                for (int ni = 0; ni < 4; ni++)
                    mma_bf16(acc[mi][ni], ah + mi * 4, wl + ni * 2);
            }
#pragma unroll
            for (int mi = 0; mi < 2; mi++)
#pragma unroll
                for (int ni = 0; ni < 4; ni++)
                    mma_bf16(acc[mi][ni], al + mi * 4, wh + ni * 2);
        }

        // ---- epilogue: fp32 partial store (disjoint per kh) ----
        float* outp = (kh ? g_acc1 : g_acc0) + (size_t)tb * B_ * C_;
        const int r0 = rt * 128 + wm * 32 + (lane >> 2);
        const int c0 = nh * 64 + wn * 32 + (lane & 3) * 2;
#pragma unroll
        for (int mi = 0; mi < 2; mi++)
#pragma unroll
            for (int ni = 0; ni < 4; ni++) {
                int row = r0 + mi * 16, col = c0 + ni * 8;
                float2 v;
                v.x = acc[mi][ni][0]; v.y = acc[mi][ni][1];
                *(float2*)(outp + (size_t)row * C_ + col) = v;
                v.x = acc[mi][ni][2]; v.y = acc[mi][ni][3];
                *(float2*)(outp + (size_t)(row + 8) * C_ + col) = v;
            }
    }
}

// ---------------- combine: acc0+acc1+bias -> Phi/Plo (t<18) or g_h ---------
__global__ void combine_kernel(const float* __restrict__ Wk_b,
                               const float* __restrict__ pb1)
{
    const int per_t = B_ * C_ / 4;
    int i = blockIdx.x * 256 + threadIdx.x;
    int t = i / per_t;
    int r = i - t * per_t;
    int c = (r & 31) << 2;

    const float4 v0 = *((const float4*)g_acc0 + i);
    const float4 v1 = *((const float4*)g_acc1 + i);
    const float* bias = (t < T_) ? (Wk_b + t * C_) : pb1;
    float s[4];
    s[0] = v0.x + v1.x + __ldg(bias + c + 0);
    s[1] = v0.y + v1.y + __ldg(bias + c + 1);
    s[2] = v0.z + v1.z + __ldg(bias + c + 2);
    s[3] = v0.w + v1.w + __ldg(bias + c + 3);

    if (t < T_) {
        __nv_bfloat162 h0, h1, l0, l1;
        h0.x = __float2bfloat16(s[0]);
        l0.x = __float2bfloat16(s[0] - __bfloat162float(h0.x));
        h0.y = __float2bfloat16(s[1]);
        l0.y = __float2bfloat16(s[1] - __bfloat162float(h0.y));
        h1.x = __float2bfloat16(s[2]);
        l1.x = __float2bfloat16(s[2] - __bfloat162float(h1.x));
        h1.y = __float2bfloat16(s[3]);
        l1.y = __float2bfloat16(s[3] - __bfloat162float(h1.y));
        size_t off = (size_t)t * B_ * C_ + (size_t)r * 4;
        *(__nv_bfloat162*)(g_Phi + off)     = h0;
        *(__nv_bfloat162*)(g_Phi + off + 2) = h1;
        *(__nv_bfloat162*)(g_Plo + off)     = l0;
        *(__nv_bfloat162*)(g_Plo + off + 2) = l1;
    } else {
        float4 o; o.x = s[0]; o.y = s[1]; o.z = s[2]; o.w = s[3];
        *((float4*)g_h + r) = o;
    }
}

// ---------------- flash NCE via mma.sync: block = 128 q-rows x t -----------
#define FST 272                     // 128 bf16 + 16B pad
#define FTILE_ (128 * FST)          // 34816
#define FL_REDM (6 * FTILE_)
#define FL_REDL (FL_REDM + 1024)
#define FL_DIAG (FL_REDL + 1024)
#define FL_SMEM (FL_DIAG + 512)     // 211456 bytes

__global__ __launch_bounds__(256, 1) void flash_mma_kernel()
{
    extern __shared__ __align__(128) char smem[];
    const uint32_t sb = smem_u32(smem);
    float* red_m = (float*)(smem + FL_REDM);
    float* red_l = (float*)(smem + FL_REDL);
    float* diag  = (float*)(smem + FL_DIAG);

    const int rb = blockIdx.x, t = blockIdx.y;
    const int tid = threadIdx.x, lane = tid & 31, wid = tid >> 5;
    const int wm = wid >> 1, wn = wid & 1;      // warp tile 32 x 64

    const __nv_bfloat16* Ehi = g_Ehi + ((size_t)t * B_ + rb * 128) * C_;
    const __nv_bfloat16* Elo = g_Elo + ((size_t)t * B_ + rb * 128) * C_;
    const __nv_bfloat16* Phi = g_Phi + (size_t)t * B_ * C_;
    const __nv_bfloat16* Plo = g_Plo + (size_t)t * B_ * C_;

#pragma unroll
    for (int f = 0; f < 8; f++) {
        int id = tid + f * 256, r = id >> 4, ch = (id & 15) << 4;
        cp16(sb + r * FST + ch,          (const char*)Ehi + r * 256 + ch);
        cp16(sb + FTILE_ + r * FST + ch, (const char*)Elo + r * 256 + ch);
    }
    CP_COMMIT();
#pragma unroll
    for (int f = 0; f < 8; f++) {
        int id = tid + f * 256, r = id >> 4, ch = (id & 15) << 4;
        cp16(sb + 2 * FTILE_ + r * FST + ch, (const char*)Phi + r * 256 + ch);
        cp16(sb + 3 * FTILE_ + r * FST + ch, (const char*)Plo + r * 256 + ch);
    }
    CP_COMMIT();

    float m_r[4], l_r[4];
#pragma unroll
    for (int r = 0; r < 4; r++) { m_r[r] = -3.0e38f; l_r[r] = 0.0f; }

    const int a_rr = wm * 32 + (lane & 15);
    const int a_kb = (lane >> 4) << 4;
    const int b_rr = wn * 64 + (lane & 7) + ((lane >> 4) << 3);
    const int b_kb = ((lane >> 3) & 1) << 4;
    const int row4 = lane >> 2;

    for (int kt = 0; kt < 16; kt++) {
        if (kt + 1 < 16) {
            uint32_t kb = sb + (2 + ((kt + 1) & 1) * 2) * FTILE_;
            const char* sh = (const char*)Phi + (size_t)(kt + 1) * 128 * 256;
            const char* sl = (const char*)Plo + (size_t)(kt + 1) * 128 * 256;
#pragma unroll
            for (int f = 0; f < 8; f++) {
                int id = tid + f * 256, r = id >> 4, ch = (id & 15) << 4;
                cp16(kb + r * FST + ch,          sh + r * 256 + ch);
                cp16(kb + FTILE_ + r * FST + ch, sl + r * 256 + ch);
            }
            CP_COMMIT();
            CP_WAIT(1);
        } else {
            CP_WAIT(0);
        }
        __syncthreads();

        const uint32_t Qh = sb, Ql = sb + FTILE_;
        const uint32_t Kh = sb + (2 + (kt & 1) * 2) * FTILE_;
        const uint32_t Kl = Kh + FTILE_;

        float acc[2][8][4];
#pragma unroll
        for (int mi = 0; mi < 2; mi++)
#pragma unroll
            for (int ni = 0; ni < 8; ni++)
#pragma unroll
                for (int q = 0; q < 4; q++) acc[mi][ni][q] = 0.0f;

#pragma unroll
        for (int k16 = 0; k16 < 8; k16++) {
            uint32_t bh[16], bl[16];
#pragma unroll
            for (int g = 0; g < 4; g++) {
                ldmx4(bh + g * 4, Kh + (b_rr + g * 16) * FST + k16 * 32 + b_kb);
                ldmx4(bl + g * 4, Kl + (b_rr + g * 16) * FST + k16 * 32 + b_kb);
            }
#pragma unroll
            for (int mi = 0; mi < 2; mi++) {
                uint32_t a[4];
                ldmx4(a, Qh + (a_rr + mi * 16) * FST + k16 * 32 + a_kb);
#pragma unroll
                for (int ni = 0; ni < 8; ni++) mma_bf16(acc[mi][ni], a, bh + ni * 2);
#pragma unroll
                for (int ni = 0; ni < 8; ni++) mma_bf16(acc[mi][ni], a, bl + ni * 2);
            }
#pragma unroll
            for (int mi = 0; mi < 2; mi++) {
                uint32_t a[4];
                ldmx4(a, Ql + (a_rr + mi * 16) * FST + k16 * 32 + a_kb);
#pragma unroll
                for (int ni = 0; ni < 8; ni++) mma_bf16(acc[mi][ni], a, bh + ni * 2);
            }
        }

        float rmax[4];
#pragma unroll
        for (int mi = 0; mi < 2; mi++)
#pragma unroll
            for (int h = 0; h < 2; h++) {
                float m = acc[mi][0][h * 2];
#pragma unroll
                for (int ni = 0; ni < 8; ni++) {
                    m = fmaxf(m, acc[mi][ni][h * 2]);
                    m = fmaxf(m, acc[mi][ni][h * 2 + 1]);
                }
                rmax[mi * 2 + h] = m;
            }
#pragma unroll
        for (int r = 0; r < 4; r++) {
            rmax[r] = fmaxf(rmax[r], __shfl_xor_sync(0xffffffffu, rmax[r], 1));
            rmax[r] = fmaxf(rmax[r], __shfl_xor_sync(0xffffffffu, rmax[r], 2));
        }
        if ((lane & 3) == 0) {
#pragma unroll
            for (int r = 0; r < 4; r++) {
                int rg = wm * 32 + (r >> 1) * 16 + row4 + (r & 1) * 8;
                red_m[rg * 2 + wn] = rmax[r];
            }
        }
        __syncthreads();

        float m_new[4], s_r[4];
#pragma unroll
        for (int r = 0; r < 4; r++) {
            int rg = wm * 32 + (r >> 1) * 16 + row4 + (r & 1) * 8;
            float tm = fmaxf(red_m[rg * 2], red_m[rg * 2 + 1]);
            m_new[r] = fmaxf(m_r[r], tm);
        }
#pragma unroll
        for (int mi = 0; mi < 2; mi++)
#pragma unroll
            for (int h = 0; h < 2; h++) {
                float mn = m_new[mi * 2 + h];
                float s = 0.0f;
#pragma unroll
                for (int ni = 0; ni < 8; ni++) {
                    s += __expf(acc[mi][ni][h * 2] - mn);
                    s += __expf(acc[mi][ni][h * 2 + 1] - mn);
                }
                s_r[mi * 2 + h] = s;
            }
#pragma unroll
        for (int r = 0; r < 4; r++) {
            s_r[r] += __shfl_xor_sync(0xffffffffu, s_r[r], 1);
            s_r[r] += __shfl_xor_sync(0xffffffffu, s_r[r], 2);
        }
        if ((lane & 3) == 0) {
#pragma unroll
            for (int r = 0; r < 4; r++) {
                int rg = wm * 32 + (r >> 1) * 16 + row4 + (r & 1) * 8;
                red_l[rg * 2 + wn] = s_r[r];
            }
        }
        if (kt == rb) {
#pragma unroll
            for (int mi = 0; mi < 2; mi++)
#pragma unroll
                for (int ni = 0; ni < 8; ni++)
#pragma unroll
                    for (int q = 0; q < 4; q++) {
                        int rl = wm * 32 + mi * 16 + row4 + (q >> 1) * 8;
                        int cl = wn * 64 + ni * 8 + (lane & 3) * 2 + (q & 1);
                        if (rl == cl) diag[rl] = acc[mi][ni][q];
                    }
        }
        __syncthreads();
#pragma unroll
        for (int r = 0; r < 4; r++) {
            int rg = wm * 32 + (r >> 1) * 16 + row4 + (r & 1) * 8;
            float ts = red_l[rg * 2] + red_l[rg * 2 + 1];
            l_r[r] = l_r[r] * __expf(m_r[r] - m_new[r]) + ts;
            m_r[r] = m_new[r];
        }
    }

    if (wn == 0 && (lane & 3) == 0) {
        float v = 0.0f;
#pragma unroll
        for (int r = 0; r < 4; r++) {
            int rg = wm * 32 + (r >> 1) * 16 + row4 + (r & 1) * 8;
            v += diag[rg] - (m_r[r] + logf(l_r[r]));
        }
        atomicAdd(&g_nce, v);
    }
}

// ---------------- BatchNorm statistics -------------------------------------
__global__ void bnstat_kernel()
{
    const int c   = blockIdx.x;
    const int tid = threadIdx.x;
    float s = 0.0f, sq = 0.0f;
    for (int b = tid; b < B_; b += 256) {
        float v = g_h[(size_t)b * C_ + c];
        s += v;
        sq = fmaf(v, v, sq);
    }
    __shared__ float ss[256], sqq[256];
    ss[tid] = s; sqq[tid] = sq;
    __syncthreads();
    for (int st = 128; st > 0; st >>= 1) {
        if (tid < st) { ss[tid] += ss[tid + st]; sqq[tid] += sqq[tid + st]; }
        __syncthreads();
    }
    if (tid == 0) {
        float mean = ss[0] * (1.0f / B_);
        float var  = sqq[0] * (1.0f / B_) - mean * mean;
        g_mean[c] = mean;
        g_rstd[c] = rsqrtf(var + 1e-5f);
    }
}

// ---------------- projection head ------------------------------------------
__global__ void proj_kernel(const float* __restrict__ gamma,
                            const float* __restrict__ beta,
                            const float* __restrict__ pw2,
                            const float* __restrict__ pb2,
                            float* __restrict__ out)
{
    __shared__ float w2s[P_][132];
    __shared__ float hn[32][129];
    __shared__ float mg[C_], bg[C_];

    const int tid  = threadIdx.x;
    const int base = blockIdx.x * 32;

    for (int f = tid; f < P_ * C_; f += 256) {
        int p = f >> 7, c = f & 127;
        w2s[p][c] = pw2[f];
    }
    if (tid < C_) {
        float sc = g_rstd[tid] * gamma[tid];
        mg[tid] = sc;
        bg[tid] = beta[tid] - g_mean[tid] * sc;
    }
    __syncthreads();

    for (int f = tid; f < 32 * C_; f += 256) {
        int r = f >> 7, c = f & 127;
        float v = g_h[(size_t)(base + r) * C_ + c];
        v = v * mg[c] + bg[c];
        v = (v >= 0.0f) ? v : 0.01f * v;
        hn[r][c] = v;
    }
    __syncthreads();

    const int r  = tid >> 3;
    const int pg = (tid & 7) * 4;
    float accp[4];
#pragma unroll
    for (int p = 0; p < 4; p++) accp[p] = 0.0f;
    for (int c = 0; c < C_; c++) {
        float hv = hn[r][c];
#pragma unroll
        for (int p = 0; p < 4; p++)
            accp[p] = fmaf(hv, w2s[pg + p][c], accp[p]);
    }
#pragma unroll
    for (int p = 0; p < 4; p++)
        out[1 + (size_t)(base + r) * P_ + pg + p] = accp[p] + pb2[pg + p];

    if (blockIdx.x == 0 && tid == 0)
        out[0] = g_nce * (-1.0f / (float)(B_ * T_));
}

// ---------------- launch ---------------------------------------------------
extern "C" void kernel_launch(void* const* d_in, const int* in_sizes, int n_in,
                              void* d_out, int out_size)
{
    const float* z     = (const float*)d_in[0];
    const float* c_t   = (const float*)d_in[1];
    const float* Wk_w  = (const float*)d_in[2];
    const float* Wk_b  = (const float*)d_in[3];
    const float* pw1   = (const float*)d_in[4];
    const float* pb1   = (const float*)d_in[5];
    const float* gamma = (const float*)d_in[6];
    const float* beta  = (const float*)d_in[7];
    const float* pw2   = (const float*)d_in[8];
    const float* pb2   = (const float*)d_in[9];
    float* out = (float*)d_out;

    init_kernel<<<(B_ * C_ + 255) / 256, 256>>>(z);
    convA_kernel<<<4096, 256>>>(c_t);
    convW_kernel<<<4864, 256>>>(Wk_w, pw1);

    gemm_mma_kernel<<<NPCTAS, 256>>>();

    combine_kernel<<<NT * B_ * C_ / 4 / 256, 256>>>(Wk_b, pb1);

    cudaFuncSetAttribute(flash_mma_kernel,
                         cudaFuncAttributeMaxDynamicSharedMemorySize, FL_SMEM);
    flash_mma_kernel<<<dim3(B_ / 128, T_), 256, FL_SMEM>>>();

    bnstat_kernel<<<C_, 256>>>();
    proj_kernel<<<B_ / 32, 256>>>(gamma, beta, pw2, pb2, out);
}